// round 4
// baseline (speedup 1.0000x reference)
// SpectralCapsules — R3.
// Post-mortem R2/R3: both failures were mechanical (undeclared locals, then the
// answer extractor compiling my markdown prose). The algorithm itself is still
// the R1-validated pipeline: act_out hit 7.8e-8, proving K1 (S = sum a^2 p p^T)
// and K2 (G = (I4 (x) W^T) S (I4 (x) W), lambda/tr ratio) are numerically exact.
// pose_out failed at rel_err 1.4948 => ~56% sign flips vs reference: jax CPU
// eigh -> LAPACK ssyevd -> (N=16 <= SMLSIZ) ssytrd('L') + ssteqr('I') + sormtr.
// Eigenvector signs are determined by that algorithm's discrete decisions
// (larfg beta sign, slartg conventions, laev2 branches, QL-vs-QR choice,
// deflation tests). K3 below is a structurally faithful fp32 emulation of that
// exact path, one warp per (b,o) problem, lane-distributed d/e/tau/c/s arrays
// via shfl, A and Z in padded shared memory.
// Prediction: pose rel_err < 1e-4 (few borderline-branch flips at worst:
// rel_err ~ 2*sqrt(k/512) would indicate k flips -> tighten deflation fidelity;
// ~1.5 again would mean wrong backend path, e.g. slartg <= 3.9 convention).
// dur_us ~ 40-80us expected, K3-dominated; optimize with ncu once passing.

#include <cuda_runtime.h>
#include <math.h>

#define FULLMASK 0xffffffffu

constexpr int Bb = 16;    // batch
constexpr int Mm = 256;   // H*W
constexpr int Cc = 544;   // channels = L*(P+1)

__device__ float g_S[Bb * 32 * 256];   // S[b][l][16][16]
__device__ float g_G[Bb * 32 * 256];   // G[b][o][16][16]
__device__ float g_tr[Bb * 32];

// ---------------------------------------------------------------------------
// K1: S[b,l] = sum_m act(b,m,l)^2 * vec(P) vec(P)^T
// ---------------------------------------------------------------------------
__global__ void k1_scatter(const float* __restrict__ in) {
    int blk = blockIdx.x;          // b*32 + l
    int b = blk >> 5, l = blk & 31;
    __shared__ float sp[32][17];
    __shared__ float sa2[32];
    int t = threadIdx.x;
    int r = t >> 4, c = t & 15;
    float acc = 0.f;
    const float* base = in + (size_t)b * Mm * Cc;
    for (int mt = 0; mt < 8; ++mt) {
        __syncthreads();
#pragma unroll
        for (int u = 0; u < 2; ++u) {
            int idx = t + u * 256;
            int mm = idx >> 4, pp = idx & 15;
            sp[mm][pp] = base[(size_t)(mt * 32 + mm) * Cc + l * 16 + pp];
        }
        if (t < 32) {
            float a = base[(size_t)(mt * 32 + t) * Cc + 512 + l];
            sa2[t] = a * a;
        }
        __syncthreads();
#pragma unroll
        for (int mm = 0; mm < 32; ++mm)
            acc = fmaf(sa2[mm] * sp[mm][r], sp[mm][c], acc);
    }
    g_S[blk * 256 + t] = acc;
}

// ---------------------------------------------------------------------------
// K2: G[b,o] = sum_l (I4 (x) W^T) S[b,l] (I4 (x) W); also trace.
// ---------------------------------------------------------------------------
__global__ void k2_gram(const float* __restrict__ wts) {
    int blk = blockIdx.x;          // b*32 + o
    int b = blk >> 5, o = blk & 31;
    __shared__ float sS[256];
    __shared__ float sH[256];
    __shared__ float sW[16];
    int t = threadIdx.x;
    int r = t >> 4, c = t & 15;
    int i = r >> 2, k = r & 3;
    int cb = c & ~3, km = c & 3;
    float g = 0.f;
    for (int l = 0; l < 32; ++l) {
        __syncthreads();
        sS[t] = g_S[(b * 32 + l) * 256 + t];
        if (t < 16) sW[t] = wts[((l * 32 + o) << 4) + t];
        __syncthreads();
        float h = 0.f;
#pragma unroll
        for (int j = 0; j < 4; ++j) h = fmaf(sS[r * 16 + cb + j], sW[j * 4 + km], h);
        sH[t] = h;
        __syncthreads();
#pragma unroll
        for (int j = 0; j < 4; ++j) g = fmaf(sW[j * 4 + k], sH[(i * 4 + j) * 16 + c], g);
    }
    g_G[blk * 256 + t] = g;
    __syncthreads();
    if (r == c) sW[r] = g;
    __syncthreads();
    if (t == 0) {
        float tr = 0.f;
#pragma unroll
        for (int p = 0; p < 16; ++p) tr += sW[p];
        g_tr[blk] = tr;
    }
}

// ---------------------------------------------------------------------------
// K3 helpers
// ---------------------------------------------------------------------------
__device__ __forceinline__ float wsum(float x) {
#pragma unroll
    for (int o = 16; o; o >>= 1) x += __shfl_xor_sync(FULLMASK, x, o);
    return x;
}
__device__ __forceinline__ float wmaxf(float x) {
#pragma unroll
    for (int o = 16; o; o >>= 1) x = fmaxf(x, __shfl_xor_sync(FULLMASK, x, o));
    return x;
}
__device__ __forceinline__ float sget(float v, int i) {
    return __shfl_sync(FULLMASK, v, i);
}
#define SSET(var, idx, val) do { float _v = (val); int _i = (idx); \
    if ((threadIdx.x & 31) == _i) var = _v; } while (0)

// LAPACK >= 3.10 slartg (real): c >= 0, r = sign(f)*hypot(f,g).
__device__ __forceinline__ void lartg(float f, float g, float& c, float& s, float& r) {
    const float RTMIN = 1.0842022e-19f;   // sqrt(safmin)
    const float RTMAX = 6.5221200e+18f;   // sqrt(safmax/2)
    if (g == 0.f)      { c = 1.f; s = 0.f; r = f; }
    else if (f == 0.f) { c = 0.f; s = copysignf(1.f, g); r = fabsf(g); }
    else {
        float f1 = fabsf(f), g1 = fabsf(g);
        if (f1 > RTMIN && f1 < RTMAX && g1 > RTMIN && g1 < RTMAX) {
            float d = sqrtf(f * f + g * g);
            c = f1 / d;
            r = copysignf(d, f);
            s = g / r;
        } else {
            float u = fminf(8.5070592e37f, fmaxf(1.17549435e-38f, fmaxf(f1, g1)));
            float fs = f / u, gs = g / u;
            float d = sqrtf(fs * fs + gs * gs);
            c = fabsf(fs) / d;
            r = copysignf(d, f) * u;
            s = g / r;
        }
    }
}

// LAPACK slaev2
__device__ __forceinline__ void laev2(float a, float b, float c,
                                      float& rt1, float& rt2, float& cs1, float& sn1) {
    float sm = a + c, df = a - c;
    float adf = fabsf(df);
    float tb = b + b;
    float ab = fabsf(tb);
    float acmx, acmn;
    if (fabsf(a) > fabsf(c)) { acmx = a; acmn = c; } else { acmx = c; acmn = a; }
    float rt;
    if (adf > ab)      rt = adf * sqrtf(1.f + (ab / adf) * (ab / adf));
    else if (adf < ab) rt = ab * sqrtf(1.f + (adf / ab) * (adf / ab));
    else               rt = ab * sqrtf(2.f);
    int sgn1;
    if (sm < 0.f)      { rt1 = 0.5f * (sm - rt); sgn1 = -1; rt2 = (acmx / rt1) * acmn - (b / rt1) * b; }
    else if (sm > 0.f) { rt1 = 0.5f * (sm + rt); sgn1 = 1;  rt2 = (acmx / rt1) * acmn - (b / rt1) * b; }
    else               { rt1 = 0.5f * rt; rt2 = -0.5f * rt; sgn1 = 1; }
    float cs; int sgn2;
    if (df >= 0.f) { cs = df + rt; sgn2 = 1; } else { cs = df - rt; sgn2 = -1; }
    float acs = fabsf(cs);
    if (acs > ab) {
        float ct = -tb / cs;
        sn1 = 1.f / sqrtf(1.f + ct * ct);
        cs1 = ct * sn1;
    } else {
        if (ab == 0.f) { cs1 = 1.f; sn1 = 0.f; }
        else {
            float tn = -cs / tb;
            cs1 = 1.f / sqrtf(1.f + tn * tn);
            sn1 = tn * cs1;
        }
    }
    if (sgn1 == sgn2) { float tn = cs1; cs1 = -sn1; sn1 = tn; }
}

// ---------------------------------------------------------------------------
// K3: faithful ssytrd('L') + ssteqr('I') + sormtr per (b,o); 1 warp each.
// ---------------------------------------------------------------------------
__global__ void __launch_bounds__(128) k3_eig(const float* __restrict__ bias,
                                              float* __restrict__ out) {
    __shared__ float shA[4][16][17];
    __shared__ float shZ[4][16][17];
    int w = threadIdx.x >> 5, lane = threadIdx.x & 31;
    int slot = blockIdx.x * 4 + w;               // b*32 + o
    float (*A)[17] = shA[w];
    float (*Z)[17] = shZ[w];
    const float* G = g_G + slot * 256;

    // jax eigh symmetrizes: A = (G + G^T)/2 ; Z = I
    if (lane < 16) {
#pragma unroll
        for (int j = 0; j < 16; ++j) A[lane][j] = 0.5f * (G[lane * 16 + j] + G[j * 16 + lane]);
#pragma unroll
        for (int j = 0; j < 16; ++j) Z[lane][j] = (lane == j) ? 1.f : 0.f;
    }
    __syncwarp();

    // lane-distributed arrays: element i lives on lane i
    float dreg = 0.f, ereg = 0.f, taureg = 0.f, cwreg = 1.f, swreg = 0.f;

    // ---- ssytrd (UPLO='L', unblocked ssytd2) ----
    for (int i = 0; i < 15; ++i) {
        float alpha = A[i + 1][i];
        float colv = (lane >= i + 2 && lane < 16) ? A[lane][i] : 0.f;
        float xnorm = sqrtf(wsum(colv * colv));
        float taui = 0.f, ei = alpha;
        if (i < 14 && xnorm != 0.f) {
            float beta = -copysignf(hypotf(alpha, xnorm), alpha);
            taui = (beta - alpha) / beta;
            float sc = 1.f / (alpha - beta);
            float vlane = colv * sc;
            if (lane == i + 1) vlane = 1.f;
            ei = beta;
            float xr = 0.f;
            for (int j = i + 1; j < 16; ++j) {
                float vj = sget(vlane, j);
                if (lane >= i + 1 && lane < 16) xr = fmaf(A[lane][j], vj, xr);
            }
            xr *= taui;
            float dotxv = wsum((lane >= i + 1 && lane < 16) ? xr * vlane : 0.f);
            float wr = fmaf(-0.5f * taui * dotxv, vlane, xr);
            __syncwarp();
            for (int j = i + 1; j < 16; ++j) {
                float vj = sget(vlane, j), wj = sget(wr, j);
                if (lane >= j && lane < 16) {
                    float val = fmaf(wr, -vj, fmaf(vlane, -wj, A[lane][j]));
                    A[lane][j] = val;
                    if (lane != j) A[j][lane] = val;
                }
            }
            __syncwarp();
            if (lane >= i + 2 && lane < 16) A[lane][i] = vlane;
            __syncwarp();
        }
        SSET(ereg, i, ei);
        SSET(taureg, i, taui);
    }
    if (lane < 16) dreg = A[lane][lane];

    // ---- ssteqr (COMPZ='I') ----
    const float EPS  = 5.9604645e-08f;
    const float EPS2 = 3.5527137e-15f;
    const float SAFMIN = 1.17549435e-38f;
    const float SSFMAX = 3.0744573e18f;
    const float SSFMIN = 3.0517578e-05f;
    int l1 = 0, jtot = 0;
    const int nmaxit = 480;

    while (l1 <= 15) {
        if (l1 > 0) SSET(ereg, l1 - 1, 0.f);
        int m = 15;
        for (int mm = l1; mm < 15; ++mm) {
            float tst = fabsf(sget(ereg, mm));
            if (tst == 0.f) { m = mm; break; }
            if (tst <= (sqrtf(fabsf(sget(dreg, mm))) * sqrtf(fabsf(sget(dreg, mm + 1)))) * EPS) {
                SSET(ereg, mm, 0.f); m = mm; break;
            }
        }
        int l = l1, lsv = l1, lend = m, lendsv = m;
        l1 = m + 1;
        if (lend == l) continue;
        float av = (lane >= l && lane <= lend && lane < 16) ? fabsf(dreg) : 0.f;
        float ae = (lane >= l && lane < lend) ? fabsf(ereg) : 0.f;
        float anorm = wmaxf(fmaxf(av, ae));
        if (anorm == 0.f) continue;
        int iscale = 0;
        if (anorm > SSFMAX) {
            iscale = 1; float sc = SSFMAX / anorm;
            if (lane >= l && lane <= lend) dreg *= sc;
            if (lane >= l && lane < lend)  ereg *= sc;
        } else if (anorm < SSFMIN) {
            iscale = 2; float sc = SSFMIN / anorm;
            if (lane >= l && lane <= lend) dreg *= sc;
            if (lane >= l && lane < lend)  ereg *= sc;
        }
        if (fabsf(sget(dreg, lend)) < fabsf(sget(dreg, l))) { int t = l; l = lend; lend = t; }

        if (lend > l) {
            // ---- QL sweeps ----
            for (;;) {
                int mq = lend;
                if (l != lend) {
                    for (int mm = l; mm < lend; ++mm) {
                        float ev = sget(ereg, mm); float tst = ev * ev;
                        if (tst <= (EPS2 * fabsf(sget(dreg, mm))) * fabsf(sget(dreg, mm + 1)) + SAFMIN) { mq = mm; break; }
                    }
                }
                if (mq < lend) SSET(ereg, mq, 0.f);
                float p = sget(dreg, l);
                if (mq == l) { l++; if (l <= lend) continue; break; }
                if (mq == l + 1) {
                    float rt1, rt2, cc, ss;
                    laev2(sget(dreg, l), sget(ereg, l), sget(dreg, l + 1), rt1, rt2, cc, ss);
                    if (lane < 16) {
                        float t = Z[lane][l + 1];
                        Z[lane][l + 1] = cc * t - ss * Z[lane][l];
                        Z[lane][l]     = ss * t + cc * Z[lane][l];
                    }
                    SSET(dreg, l, rt1); SSET(dreg, l + 1, rt2); SSET(ereg, l, 0.f);
                    l += 2; if (l <= lend) continue; break;
                }
                if (jtot >= nmaxit) break;
                jtot++;
                float el = sget(ereg, l);
                float gg = (sget(dreg, l + 1) - p) / (2.f * el);
                float rr = hypotf(gg, 1.f);
                gg = sget(dreg, mq) - p + el / (gg + copysignf(rr, gg));
                float ss = 1.f, cc = 1.f; p = 0.f;
                for (int i = mq - 1; i >= l; --i) {
                    float ei = sget(ereg, i);
                    float ff = ss * ei, bb = cc * ei;
                    lartg(gg, ff, cc, ss, rr);
                    if (i != mq - 1) SSET(ereg, i + 1, rr);
                    gg = sget(dreg, i + 1) - p;
                    rr = (sget(dreg, i) - gg) * ss + 2.f * cc * bb;
                    p = ss * rr;
                    SSET(dreg, i + 1, gg + p);
                    gg = cc * rr - bb;
                    SSET(cwreg, i, cc); SSET(swreg, i, -ss);
                }
                for (int jj = mq - 1; jj >= l; --jj) {
                    float cj = sget(cwreg, jj), sj = sget(swreg, jj);
                    if (lane < 16) {
                        float t = Z[lane][jj + 1];
                        Z[lane][jj + 1] = cj * t - sj * Z[lane][jj];
                        Z[lane][jj]     = sj * t + cj * Z[lane][jj];
                    }
                }
                SSET(dreg, l, sget(dreg, l) - p);
                SSET(ereg, l, gg);
            }
        } else {
            // ---- QR sweeps ----
            for (;;) {
                int mq = lend;
                if (l != lend) {
                    for (int mm = l; mm > lend; --mm) {
                        float ev = sget(ereg, mm - 1); float tst = ev * ev;
                        if (tst <= (EPS2 * fabsf(sget(dreg, mm))) * fabsf(sget(dreg, mm - 1)) + SAFMIN) { mq = mm; break; }
                    }
                }
                if (mq > lend) SSET(ereg, mq - 1, 0.f);
                float p = sget(dreg, l);
                if (mq == l) { l--; if (l >= lend) continue; break; }
                if (mq == l - 1) {
                    float rt1, rt2, cc, ss;
                    laev2(sget(dreg, l - 1), sget(ereg, l - 1), sget(dreg, l), rt1, rt2, cc, ss);
                    if (lane < 16) {
                        float t = Z[lane][l];
                        Z[lane][l]     = cc * t - ss * Z[lane][l - 1];
                        Z[lane][l - 1] = ss * t + cc * Z[lane][l - 1];
                    }
                    SSET(dreg, l - 1, rt1); SSET(dreg, l, rt2); SSET(ereg, l - 1, 0.f);
                    l -= 2; if (l >= lend) continue; break;
                }
                if (jtot >= nmaxit) break;
                jtot++;
                float el = sget(ereg, l - 1);
                float gg = (sget(dreg, l - 1) - p) / (2.f * el);
                float rr = hypotf(gg, 1.f);
                gg = sget(dreg, mq) - p + el / (gg + copysignf(rr, gg));
                float ss = 1.f, cc = 1.f; p = 0.f;
                for (int i = mq; i < l; ++i) {
                    float ei = sget(ereg, i);
                    float ff = ss * ei, bb = cc * ei;
                    lartg(gg, ff, cc, ss, rr);
                    if (i != mq) SSET(ereg, i - 1, rr);
                    gg = sget(dreg, i) - p;
                    rr = (sget(dreg, i + 1) - gg) * ss + 2.f * cc * bb;
                    p = ss * rr;
                    SSET(dreg, i, gg + p);
                    gg = cc * rr - bb;
                    SSET(cwreg, i, cc); SSET(swreg, i, ss);
                }
                for (int jj = mq; jj < l; ++jj) {
                    float cj = sget(cwreg, jj), sj = sget(swreg, jj);
                    if (lane < 16) {
                        float t = Z[lane][jj + 1];
                        Z[lane][jj + 1] = cj * t - sj * Z[lane][jj];
                        Z[lane][jj]     = sj * t + cj * Z[lane][jj];
                    }
                }
                SSET(dreg, l, sget(dreg, l) - p);
                SSET(ereg, l - 1, gg);
            }
        }
        if (iscale == 1) {
            float sc = anorm / SSFMAX;
            if (lane >= lsv && lane <= lendsv) dreg *= sc;
            if (lane >= lsv && lane < lendsv)  ereg *= sc;
        } else if (iscale == 2) {
            float sc = anorm / SSFMIN;
            if (lane >= lsv && lane <= lendsv) dreg *= sc;
            if (lane >= lsv && lane < lendsv)  ereg *= sc;
        }
    }

    // ---- sormtr: Z := H(1)...H(n-1) Z ----
    __syncwarp();
    for (int i = 14; i >= 0; --i) {
        float ti = sget(taureg, i);
        if (ti != 0.f) {
            float vlane = (lane == i + 1) ? 1.f
                        : ((lane >= i + 2 && lane < 16) ? A[lane][i] : 0.f);
            float wj = 0.f;
            for (int r = i + 1; r < 16; ++r) {
                float vr = sget(vlane, r);
                if (lane < 16) wj = fmaf(vr, Z[r][lane], wj);
            }
            wj *= ti;
            __syncwarp();
            for (int j = 0; j < 16; ++j) {
                float wjj = sget(wj, j);
                if (lane < 16) Z[lane][j] = fmaf(-vlane, wjj, Z[lane][j]);
            }
            __syncwarp();
        }
    }

    // ---- argmax eigenvalue, outputs ----
    float dv = (lane < 16) ? dreg : -3.4e38f;
    int idx = lane;
#pragma unroll
    for (int off = 16; off; off >>= 1) {
        float vo = __shfl_xor_sync(FULLMASK, dv, off);
        int io = __shfl_xor_sync(FULLMASK, idx, off);
        if (vo > dv || (vo == dv && io < idx)) { dv = vo; idx = io; }
    }
    int cmax = idx;
    float lam = sget(dreg, cmax);
    float tr = g_tr[slot];
    int o = slot & 31;
    if (lane == 0) out[slot] = 1.f / (1.f + expf(-(lam / tr - bias[o])));
    if (lane < 16) out[512 + slot * 16 + lane] = Z[lane][cmax];
}

// ---------------------------------------------------------------------------
extern "C" void kernel_launch(void* const* d_in, const int* in_sizes, int n_in,
                              void* d_out, int out_size) {
    const float* in   = (const float*)d_in[0];
    const float* wts  = (const float*)d_in[1];
    const float* bias = (const float*)d_in[2];
    float* out = (float*)d_out;
    k1_scatter<<<512, 256>>>(in);
    k2_gram<<<512, 256>>>(wts);
    k3_eig<<<128, 128>>>(bias, out);
}

// round 5
// speedup vs baseline: 1.4919x; 1.4919x over previous
// SpectralCapsules R5: optimize the passing R4 pipeline (129us -> target ~60us).
// K1: upper-triangle only (bit-identical entries, mirrored store).
// K2: full weight preload + one-iteration gmem prefetch (identical numerics).
// K3: fused Z rotations w/ carry register, ballot deflation scans, fdividef in
//     the serial QL/QR chain, pipelined shfls, fully unrolled ssytrd/sormtr.
#include <cuda_runtime.h>
#include <math.h>

#define FULLMASK 0xffffffffu

constexpr int Bb = 16;    // batch
constexpr int Mm = 256;   // H*W
constexpr int Cc = 544;   // channels = L*(P+1)

__device__ float g_S[Bb * 32 * 256];   // S[b][l][16][16]
__device__ float g_G[Bb * 32 * 256];   // G[b][o][16][16]
__device__ float g_tr[Bb * 32];

// ---------------------------------------------------------------------------
// K1: S[b,l] = sum_m act^2 * vec(P) vec(P)^T  -- upper triangle only (136
// entries by threads 0..135 of a 160-thread block), mirrored at store.
// Per-entry accumulation order identical to R4 -> bit-identical g_S.
// ---------------------------------------------------------------------------
__global__ void k1_scatter(const float* __restrict__ in) {
    int blk = blockIdx.x;          // b*32 + l
    int b = blk >> 5, l = blk & 31;
    __shared__ float sp[32][17];
    __shared__ float sa2[32];
    int t = threadIdx.x;           // 0..159
    int tt = t < 136 ? t : 135;
    int r = (int)((33.0f - sqrtf((float)(1089 - 8 * tt))) * 0.5f + 1e-4f);
    int c = tt - ((r * (33 - r)) >> 1) + r;
    float acc = 0.f;
    const float* base = in + (size_t)b * Mm * Cc;
    for (int mt = 0; mt < 8; ++mt) {
        __syncthreads();
        for (int idx = t; idx < 512; idx += 160) {
            int mm = idx >> 4, pp = idx & 15;
            sp[mm][pp] = base[(size_t)(mt * 32 + mm) * Cc + l * 16 + pp];
        }
        if (t < 32) {
            float a = base[(size_t)(mt * 32 + t) * Cc + 512 + l];
            sa2[t] = a * a;
        }
        __syncthreads();
#pragma unroll
        for (int mm = 0; mm < 32; ++mm)
            acc = fmaf(sa2[mm] * sp[mm][r], sp[mm][c], acc);
    }
    if (t < 136) {
        g_S[blk * 256 + r * 16 + c] = acc;
        g_S[blk * 256 + c * 16 + r] = acc;
    }
}

// ---------------------------------------------------------------------------
// K2: G[b,o] = sum_l (I4 (x) W^T) S[b,l] (I4 (x) W); trace. Weight preload +
// next-l prefetch. Accumulation order identical to R4.
// ---------------------------------------------------------------------------
__global__ void k2_gram(const float* __restrict__ wts) {
    int blk = blockIdx.x;          // b*32 + o
    int b = blk >> 5, o = blk & 31;
    __shared__ float sS[256];
    __shared__ float sH[256];
    __shared__ float sW[512];      // [l][16] for all 32 l
    int t = threadIdx.x;
    int r = t >> 4, c = t & 15;
    int i = r >> 2, k = r & 3;
    int cb = c & ~3, km = c & 3;
    // preload all weights for this o
    sW[t]       = wts[((( (t >> 4)     ) * 32 + o) << 4) + (t & 15)];
    sW[t + 256] = wts[((( (t >> 4) + 16) * 32 + o) << 4) + (t & 15)];
    float pre = g_S[(b * 32) * 256 + t];
    float g = 0.f;
    float trpart = 0.f;
    for (int l = 0; l < 32; ++l) {
        sS[t] = pre;
        __syncthreads();           // sS + (first iter) sW visible
        if (l < 31) pre = g_S[(b * 32 + l + 1) * 256 + t];
        const float* wv = &sW[l * 16];
        float h = 0.f;
#pragma unroll
        for (int j = 0; j < 4; ++j) h = fmaf(sS[r * 16 + cb + j], wv[j * 4 + km], h);
        sH[t] = h;
        __syncthreads();
#pragma unroll
        for (int j = 0; j < 4; ++j) g = fmaf(wv[j * 4 + k], sH[(i * 4 + j) * 16 + c], g);
    }
    g_G[blk * 256 + t] = g;
    __syncthreads();
    if (r == c) sS[r] = g;         // reuse sS for diagonal
    __syncthreads();
    if (t == 0) {
        float tr = 0.f;
#pragma unroll
        for (int p = 0; p < 16; ++p) tr += sS[p];
        g_tr[blk] = tr;
    }
    (void)trpart;
}

// ---------------------------------------------------------------------------
// K3 helpers
// ---------------------------------------------------------------------------
__device__ __forceinline__ float wsum(float x) {
#pragma unroll
    for (int o = 16; o; o >>= 1) x += __shfl_xor_sync(FULLMASK, x, o);
    return x;
}
__device__ __forceinline__ float wmaxf(float x) {
#pragma unroll
    for (int o = 16; o; o >>= 1) x = fmaxf(x, __shfl_xor_sync(FULLMASK, x, o));
    return x;
}
__device__ __forceinline__ float sget(float v, int i) {
    return __shfl_sync(FULLMASK, v, i);
}
#define SSET(var, idx, val) do { float _v = (val); int _i = (idx); \
    if ((threadIdx.x & 31) == _i) var = _v; } while (0)

// LAPACK >= 3.10 slartg, fast path with __fdividef (2-ulp; branch-safe here).
__device__ __forceinline__ void lartg(float f, float g, float& c, float& s, float& r) {
    if (g == 0.f)      { c = 1.f; s = 0.f; r = f; }
    else if (f == 0.f) { c = 0.f; s = copysignf(1.f, g); r = fabsf(g); }
    else {
        float f1 = fabsf(f), g1 = fabsf(g);
        float d = sqrtf(f * f + g * g);
        c = __fdividef(f1, d);
        r = copysignf(d, f);
        s = __fdividef(g, r);
        (void)g1;
    }
}

// LAPACK slaev2 (rare path: keep precise arithmetic)
__device__ __forceinline__ void laev2(float a, float b, float c,
                                      float& rt1, float& rt2, float& cs1, float& sn1) {
    float sm = a + c, df = a - c;
    float adf = fabsf(df);
    float tb = b + b;
    float ab = fabsf(tb);
    float acmx, acmn;
    if (fabsf(a) > fabsf(c)) { acmx = a; acmn = c; } else { acmx = c; acmn = a; }
    float rt;
    if (adf > ab)      rt = adf * sqrtf(1.f + (ab / adf) * (ab / adf));
    else if (adf < ab) rt = ab * sqrtf(1.f + (adf / ab) * (adf / ab));
    else               rt = ab * sqrtf(2.f);
    int sgn1;
    if (sm < 0.f)      { rt1 = 0.5f * (sm - rt); sgn1 = -1; rt2 = (acmx / rt1) * acmn - (b / rt1) * b; }
    else if (sm > 0.f) { rt1 = 0.5f * (sm + rt); sgn1 = 1;  rt2 = (acmx / rt1) * acmn - (b / rt1) * b; }
    else               { rt1 = 0.5f * rt; rt2 = -0.5f * rt; sgn1 = 1; }
    float cs; int sgn2;
    if (df >= 0.f) { cs = df + rt; sgn2 = 1; } else { cs = df - rt; sgn2 = -1; }
    float acs = fabsf(cs);
    if (acs > ab) {
        float ct = -tb / cs;
        sn1 = 1.f / sqrtf(1.f + ct * ct);
        cs1 = ct * sn1;
    } else {
        if (ab == 0.f) { cs1 = 1.f; sn1 = 0.f; }
        else {
            float tn = -cs / tb;
            cs1 = 1.f / sqrtf(1.f + tn * tn);
            sn1 = tn * cs1;
        }
    }
    if (sgn1 == sgn2) { float tn = cs1; cs1 = -sn1; sn1 = tn; }
}

// ---------------------------------------------------------------------------
// K3: ssytrd('L') + ssteqr('I') + sormtr, 1 warp per (b,o).
// ---------------------------------------------------------------------------
__global__ void __launch_bounds__(128) k3_eig(const float* __restrict__ bias,
                                              float* __restrict__ out) {
    __shared__ float shA[4][16][17];
    __shared__ float shZ[4][16][17];
    int w = threadIdx.x >> 5, lane = threadIdx.x & 31;
    int slot = blockIdx.x * 4 + w;               // b*32 + o
    float (*A)[17] = shA[w];
    float (*Z)[17] = shZ[w];
    const float* G = g_G + slot * 256;
    int lr = lane & 15;

    if (lane < 16) {
#pragma unroll
        for (int j = 0; j < 16; ++j) A[lane][j] = 0.5f * (G[lane * 16 + j] + G[j * 16 + lane]);
#pragma unroll
        for (int j = 0; j < 16; ++j) Z[lane][j] = (lane == j) ? 1.f : 0.f;
    }
    __syncwarp();

    float dreg = 0.f, ereg = 0.f, taureg = 0.f;

    // ---- ssytrd (UPLO='L', unblocked). j-loops unrolled 0..15: out-of-range
    // terms have v=w=0 exactly, and fmaf(x,0,acc)==acc for finite x.
    for (int i = 0; i < 15; ++i) {
        float alpha = A[i + 1][i];
        float colv = (lane >= i + 2 && lane < 16) ? A[lane][i] : 0.f;
        float xnorm = sqrtf(wsum(colv * colv));
        float taui = 0.f, ei = alpha;
        if (i < 14 && xnorm != 0.f) {
            float beta = -copysignf(hypotf(alpha, xnorm), alpha);
            taui = (beta - alpha) / beta;
            float sc = 1.f / (alpha - beta);
            float vlane = colv * sc;
            if (lane == i + 1) vlane = 1.f;
            ei = beta;
            float xr = 0.f;
#pragma unroll
            for (int j = 0; j < 16; ++j) {
                float vj = sget(vlane, j);
                xr = fmaf(A[lr][j], vj, xr);
            }
            xr = (lane >= i + 1 && lane < 16) ? xr * taui : 0.f;
            float dotxv = wsum(xr * vlane);
            float wr = fmaf(-0.5f * taui * dotxv, vlane, xr);
            __syncwarp();
#pragma unroll
            for (int j = 0; j < 16; ++j) {
                float vj = sget(vlane, j), wj = sget(wr, j);
                if (lane >= j && lane < 16) {
                    float val = fmaf(wr, -vj, fmaf(vlane, -wj, A[lane][j]));
                    A[lane][j] = val;
                    if (lane != j) A[j][lane] = val;
                }
            }
            __syncwarp();
            if (lane >= i + 2 && lane < 16) A[lane][i] = vlane;
            __syncwarp();
        }
        SSET(ereg, i, ei);
        SSET(taureg, i, taui);
    }
    if (lane < 16) dreg = A[lane][lane];

    // ---- ssteqr (COMPZ='I'), ballot scans + fused Z rotations ----
    const float EPS  = 5.9604645e-08f;
    const float EPS2 = 3.5527137e-15f;
    const float SAFMIN = 1.17549435e-38f;
    const float SSFMAX = 3.0744573e18f;
    const float SSFMIN = 3.0517578e-05f;
    int l1 = 0, jtot = 0;
    const int nmaxit = 480;

    while (l1 <= 15) {
        if (l1 > 0) SSET(ereg, l1 - 1, 0.f);
        int m;
        {
            float dnext = __shfl_down_sync(FULLMASK, dreg, 1);
            float tst = fabsf(ereg);
            bool stop = (lane >= l1 && lane < 15) &&
                (tst == 0.f || tst <= (sqrtf(fabsf(dreg)) * sqrtf(fabsf(dnext))) * EPS);
            unsigned msk = __ballot_sync(FULLMASK, stop);
            m = msk ? (__ffs(msk) - 1) : 15;
            if (m < 15) SSET(ereg, m, 0.f);
        }
        int l = l1, lsv = l1, lend = m, lendsv = m;
        l1 = m + 1;
        if (lend == l) continue;
        float av = (lane >= l && lane <= lend && lane < 16) ? fabsf(dreg) : 0.f;
        float ae = (lane >= l && lane < lend) ? fabsf(ereg) : 0.f;
        float anorm = wmaxf(fmaxf(av, ae));
        if (anorm == 0.f) continue;
        int iscale = 0;
        if (anorm > SSFMAX) {
            iscale = 1; float sc = SSFMAX / anorm;
            if (lane >= l && lane <= lend) dreg *= sc;
            if (lane >= l && lane < lend)  ereg *= sc;
        } else if (anorm < SSFMIN) {
            iscale = 2; float sc = SSFMIN / anorm;
            if (lane >= l && lane <= lend) dreg *= sc;
            if (lane >= l && lane < lend)  ereg *= sc;
        }
        if (fabsf(sget(dreg, lend)) < fabsf(sget(dreg, l))) { int tmp = l; l = lend; lend = tmp; }

        if (lend > l) {
            // ---- QL sweeps ----
            for (;;) {
                int mq;
                {
                    float dnext = __shfl_down_sync(FULLMASK, dreg, 1);
                    bool stop = (lane >= l && lane < lend) &&
                        (ereg * ereg <= (EPS2 * fabsf(dreg)) * fabsf(dnext) + SAFMIN);
                    unsigned msk = __ballot_sync(FULLMASK, stop);
                    mq = msk ? (__ffs(msk) - 1) : lend;
                }
                if (mq < lend) SSET(ereg, mq, 0.f);
                float p = sget(dreg, l);
                if (mq == l) { l++; if (l <= lend) continue; break; }
                if (mq == l + 1) {
                    float rt1, rt2, cc, ss;
                    laev2(sget(dreg, l), sget(ereg, l), sget(dreg, l + 1), rt1, rt2, cc, ss);
                    if (lane < 16) {
                        float t = Z[lane][l + 1];
                        Z[lane][l + 1] = cc * t - ss * Z[lane][l];
                        Z[lane][l]     = ss * t + cc * Z[lane][l];
                    }
                    SSET(dreg, l, rt1); SSET(dreg, l + 1, rt2); SSET(ereg, l, 0.f);
                    l += 2; if (l <= lend) continue; break;
                }
                if (jtot >= nmaxit) break;
                jtot++;
                float el = sget(ereg, l);
                float gg = __fdividef(sget(dreg, l + 1) - p, 2.f * el);
                float rr = sqrtf(fmaf(gg, gg, 1.f));
                gg = sget(dreg, mq) - p + __fdividef(el, gg + copysignf(rr, gg));
                float ss = 1.f, cc = 1.f; p = 0.f;
                float carry = (lane < 16) ? Z[lane][mq] : 0.f;
                float dI1 = sget(dreg, mq);      // pre-sweep d[i+1] for i=mq-1
                for (int i = mq - 1; i >= l; --i) {
                    float eI = sget(ereg, i);    // all reads are pre-sweep values
                    float dI = sget(dreg, i);
                    float ff = ss * eI, bb = cc * eI;
                    lartg(gg, ff, cc, ss, rr);
                    if (i != mq - 1) SSET(ereg, i + 1, rr);
                    gg = dI1 - p;
                    rr = (dI - gg) * ss + 2.f * cc * bb;
                    p = ss * rr;
                    SSET(dreg, i + 1, gg + p);
                    gg = cc * rr - bb;
                    // fused rotation on Z cols (i+1, i): cj=cc, sj=-ss
                    if (lane < 16) {
                        float zlo = Z[lane][i];
                        Z[lane][i + 1] = fmaf(cc, carry, ss * zlo);
                        carry = fmaf(cc, zlo, -ss * carry);
                    }
                    dI1 = dI;
                }
                if (lane < 16) Z[lane][l] = carry;
                SSET(dreg, l, sget(dreg, l) - p);
                SSET(ereg, l, gg);
            }
        } else {
            // ---- QR sweeps ----
            for (;;) {
                int mq;
                {
                    float dnext = __shfl_down_sync(FULLMASK, dreg, 1);
                    bool stop = (lane >= lend && lane < l) &&
                        (ereg * ereg <= (EPS2 * fabsf(dnext)) * fabsf(dreg) + SAFMIN);
                    unsigned msk = __ballot_sync(FULLMASK, stop);
                    mq = msk ? (31 - __clz(msk)) + 1 : lend;
                }
                if (mq > lend) SSET(ereg, mq - 1, 0.f);
                float p = sget(dreg, l);
                if (mq == l) { l--; if (l >= lend) continue; break; }
                if (mq == l - 1) {
                    float rt1, rt2, cc, ss;
                    laev2(sget(dreg, l - 1), sget(ereg, l - 1), sget(dreg, l), rt1, rt2, cc, ss);
                    if (lane < 16) {
                        float t = Z[lane][l];
                        Z[lane][l]     = cc * t - ss * Z[lane][l - 1];
                        Z[lane][l - 1] = ss * t + cc * Z[lane][l - 1];
                    }
                    SSET(dreg, l - 1, rt1); SSET(dreg, l, rt2); SSET(ereg, l - 1, 0.f);
                    l -= 2; if (l >= lend) continue; break;
                }
                if (jtot >= nmaxit) break;
                jtot++;
                float el = sget(ereg, l - 1);
                float gg = __fdividef(sget(dreg, l - 1) - p, 2.f * el);
                float rr = sqrtf(fmaf(gg, gg, 1.f));
                gg = sget(dreg, mq) - p + __fdividef(el, gg + copysignf(rr, gg));
                float ss = 1.f, cc = 1.f; p = 0.f;
                float carry = (lane < 16) ? Z[lane][mq] : 0.f;
                float dI = sget(dreg, mq);       // pre-sweep d[i] for i=mq
                for (int i = mq; i < l; ++i) {
                    float eI = sget(ereg, i);
                    float dI1 = sget(dreg, i + 1);
                    float ff = ss * eI, bb = cc * eI;
                    lartg(gg, ff, cc, ss, rr);
                    if (i != mq) SSET(ereg, i - 1, rr);
                    gg = dI - p;
                    rr = (dI1 - gg) * ss + 2.f * cc * bb;
                    p = ss * rr;
                    SSET(dreg, i, gg + p);
                    gg = cc * rr - bb;
                    // fused rotation on Z cols (i, i+1): sj=+ss
                    if (lane < 16) {
                        float zhi = Z[lane][i + 1];
                        Z[lane][i] = fmaf(ss, zhi, cc * carry);
                        carry = fmaf(cc, zhi, -ss * carry);
                    }
                    dI = dI1;
                }
                if (lane < 16) Z[lane][l] = carry;
                SSET(dreg, l, sget(dreg, l) - p);
                SSET(ereg, l - 1, gg);
            }
        }
        if (iscale == 1) {
            float sc = anorm / SSFMAX;
            if (lane >= lsv && lane <= lendsv) dreg *= sc;
            if (lane >= lsv && lane < lendsv)  ereg *= sc;
        } else if (iscale == 2) {
            float sc = anorm / SSFMIN;
            if (lane >= lsv && lane <= lendsv) dreg *= sc;
            if (lane >= lsv && lane < lendsv)  ereg *= sc;
        }
    }

    // ---- sormtr: Z := H(1)...H(n-1) Z (unrolled; zero-padded terms exact) ----
    __syncwarp();
    for (int i = 14; i >= 0; --i) {
        float ti = sget(taureg, i);
        if (ti != 0.f) {
            float vlane = (lane == i + 1) ? 1.f
                        : ((lane >= i + 2 && lane < 16) ? A[lane][i] : 0.f);
            float wj = 0.f;
#pragma unroll
            for (int r = 0; r < 16; ++r) {
                float vr = sget(vlane, r);
                wj = fmaf(vr, Z[r][lr], wj);
            }
            wj *= ti;
            __syncwarp();
#pragma unroll
            for (int j = 0; j < 16; ++j) {
                float wjj = sget(wj, j);
                if (lane < 16) Z[lane][j] = fmaf(-vlane, wjj, Z[lane][j]);
            }
            __syncwarp();
        }
    }

    // ---- argmax eigenvalue, outputs ----
    float dv = (lane < 16) ? dreg : -3.4e38f;
    int idx = lane;
#pragma unroll
    for (int off = 16; off; off >>= 1) {
        float vo = __shfl_xor_sync(FULLMASK, dv, off);
        int io = __shfl_xor_sync(FULLMASK, idx, off);
        if (vo > dv || (vo == dv && io < idx)) { dv = vo; idx = io; }
    }
    int cmax = idx;
    float lam = sget(dreg, cmax);
    float tr = g_tr[slot];
    int o = slot & 31;
    if (lane == 0) out[slot] = 1.f / (1.f + expf(-(lam / tr - bias[o])));
    if (lane < 16) out[512 + slot * 16 + lane] = Z[lane][cmax];
}

// ---------------------------------------------------------------------------
extern "C" void kernel_launch(void* const* d_in, const int* in_sizes, int n_in,
                              void* d_out, int out_size) {
    const float* in   = (const float*)d_in[0];
    const float* wts  = (const float*)d_in[1];
    const float* bias = (const float*)d_in[2];
    float* out = (float*)d_out;
    k1_scatter<<<512, 160>>>(in);
    k2_gram<<<512, 256>>>(wts);
    k3_eig<<<128, 128>>>(bias, out);
}

// round 6
// speedup vs baseline: 1.5901x; 1.0658x over previous
// SpectralCapsules R6: k1 split-m (4 chunks) + float4 single-phase load,
// k1b fixed-order partial reduce, k3 software-pipelined QL/QR with rsqrt lartg.
#include <cuda_runtime.h>
#include <math.h>

#define FULLMASK 0xffffffffu

constexpr int Bb = 16;    // batch
constexpr int Mm = 256;   // H*W
constexpr int Cc = 544;   // channels = L*(P+1)

__device__ float g_Sp[Bb * 32 * 4 * 256]; // partial S per m-chunk
__device__ float g_S[Bb * 32 * 256];      // S[b][l][16][16]
__device__ float g_G[Bb * 32 * 256];      // G[b][o][16][16]
__device__ float g_tr[Bb * 32];

// ---------------------------------------------------------------------------
// K1a: partial S over 64 m per block. One float4 load per thread, one sync,
// one 64-step serial FMA chain per entry (order within chunk = m ascending).
// ---------------------------------------------------------------------------
__global__ void __launch_bounds__(256) k1a(const float* __restrict__ in) {
    int blk = blockIdx.x;               // ((b*32+l)*4 + chunk)
    int chunk = blk & 3;
    int bl = blk >> 2;
    int b = bl >> 5, l = bl & 31;
    __shared__ float sp[64 * 16];
    __shared__ float sa2[64];
    int t = threadIdx.x;
    const float* base = in + (size_t)b * Mm * Cc + (size_t)chunk * 64 * Cc;
    {
        int mm = t >> 2, q = t & 3;     // 64 m x 4 quads
        const float4* src = (const float4*)(base + (size_t)mm * Cc + l * 16) + q;
        ((float4*)sp)[mm * 4 + q] = *src;
    }
    if (t < 64) {
        float a = base[(size_t)t * Cc + 512 + l];
        sa2[t] = a * a;
    }
    __syncthreads();
    int r = t >> 4, c = t & 15;
    float acc = 0.f;
#pragma unroll
    for (int mm = 0; mm < 64; ++mm)
        acc = fmaf(sa2[mm] * sp[mm * 16 + r], sp[mm * 16 + c], acc);
    g_Sp[blk * 256 + t] = acc;
}

// K1b: S = ((p0 + p1) + p2) + p3  (fixed order)
__global__ void __launch_bounds__(256) k1b() {
    int blk = blockIdx.x;               // b*32 + l
    int t = threadIdx.x;
    const float* p = g_Sp + blk * 4 * 256;
    g_S[blk * 256 + t] = ((p[t] + p[256 + t]) + p[512 + t]) + p[768 + t];
}

// ---------------------------------------------------------------------------
// K2: G[b,o] = sum_l (I4 (x) W^T) S[b,l] (I4 (x) W); trace. (unchanged R5)
// ---------------------------------------------------------------------------
__global__ void k2_gram(const float* __restrict__ wts) {
    int blk = blockIdx.x;          // b*32 + o
    int b = blk >> 5, o = blk & 31;
    __shared__ float sS[256];
    __shared__ float sH[256];
    __shared__ float sW[512];
    int t = threadIdx.x;
    int r = t >> 4, c = t & 15;
    int i = r >> 2, k = r & 3;
    int cb = c & ~3, km = c & 3;
    sW[t]       = wts[(((t >> 4)     ) * 32 + o) * 16 + (t & 15)];
    sW[t + 256] = wts[(((t >> 4) + 16) * 32 + o) * 16 + (t & 15)];
    float pre = g_S[(b * 32) * 256 + t];
    float g = 0.f;
    for (int l = 0; l < 32; ++l) {
        sS[t] = pre;
        __syncthreads();
        if (l < 31) pre = g_S[(b * 32 + l + 1) * 256 + t];
        const float* wv = &sW[l * 16];
        float h = 0.f;
#pragma unroll
        for (int j = 0; j < 4; ++j) h = fmaf(sS[r * 16 + cb + j], wv[j * 4 + km], h);
        sH[t] = h;
        __syncthreads();
#pragma unroll
        for (int j = 0; j < 4; ++j) g = fmaf(wv[j * 4 + k], sH[(i * 4 + j) * 16 + c], g);
    }
    g_G[blk * 256 + t] = g;
    __syncthreads();
    if (r == c) sS[r] = g;
    __syncthreads();
    if (t == 0) {
        float tr = 0.f;
#pragma unroll
        for (int p2 = 0; p2 < 16; ++p2) tr += sS[p2];
        g_tr[blk] = tr;
    }
}

// ---------------------------------------------------------------------------
// K3 helpers
// ---------------------------------------------------------------------------
__device__ __forceinline__ float wsum(float x) {
#pragma unroll
    for (int o = 16; o; o >>= 1) x += __shfl_xor_sync(FULLMASK, x, o);
    return x;
}
__device__ __forceinline__ float wmaxf(float x) {
#pragma unroll
    for (int o = 16; o; o >>= 1) x = fmaxf(x, __shfl_xor_sync(FULLMASK, x, o));
    return x;
}
__device__ __forceinline__ float sget(float v, int i) {
    return __shfl_sync(FULLMASK, v, i);
}
#define SSET(var, idx, val) do { float _v = (val); int _i = (idx); \
    if ((threadIdx.x & 31) == _i) var = _v; } while (0)

// lartg fast path via rsqrt (ulp-level vs divides; branch decisions continuous)
__device__ __forceinline__ void lartg(float f, float g, float& c, float& s, float& r) {
    if (g == 0.f)      { c = 1.f; s = 0.f; r = f; }
    else if (f == 0.f) { c = 0.f; s = copysignf(1.f, g); r = fabsf(g); }
    else {
        float t2 = fmaf(f, f, g * g);
        float rinv = rsqrtf(t2);
        float d = t2 * rinv;
        c = fabsf(f) * rinv;
        r = copysignf(d, f);
        s = g * rinv * copysignf(1.f, f);
    }
}

// LAPACK slaev2 (rare path: keep precise arithmetic)
__device__ __forceinline__ void laev2(float a, float b, float c,
                                      float& rt1, float& rt2, float& cs1, float& sn1) {
    float sm = a + c, df = a - c;
    float adf = fabsf(df);
    float tb = b + b;
    float ab = fabsf(tb);
    float acmx, acmn;
    if (fabsf(a) > fabsf(c)) { acmx = a; acmn = c; } else { acmx = c; acmn = a; }
    float rt;
    if (adf > ab)      rt = adf * sqrtf(1.f + (ab / adf) * (ab / adf));
    else if (adf < ab) rt = ab * sqrtf(1.f + (adf / ab) * (adf / ab));
    else               rt = ab * sqrtf(2.f);
    int sgn1;
    if (sm < 0.f)      { rt1 = 0.5f * (sm - rt); sgn1 = -1; rt2 = (acmx / rt1) * acmn - (b / rt1) * b; }
    else if (sm > 0.f) { rt1 = 0.5f * (sm + rt); sgn1 = 1;  rt2 = (acmx / rt1) * acmn - (b / rt1) * b; }
    else               { rt1 = 0.5f * rt; rt2 = -0.5f * rt; sgn1 = 1; }
    float cs; int sgn2;
    if (df >= 0.f) { cs = df + rt; sgn2 = 1; } else { cs = df - rt; sgn2 = -1; }
    float acs = fabsf(cs);
    if (acs > ab) {
        float ct = -tb / cs;
        sn1 = 1.f / sqrtf(1.f + ct * ct);
        cs1 = ct * sn1;
    } else {
        if (ab == 0.f) { cs1 = 1.f; sn1 = 0.f; }
        else {
            float tn = -cs / tb;
            cs1 = 1.f / sqrtf(1.f + tn * tn);
            sn1 = tn * cs1;
        }
    }
    if (sgn1 == sgn2) { float tn = cs1; cs1 = -sn1; sn1 = tn; }
}

// ---------------------------------------------------------------------------
// K3: ssytrd('L') + ssteqr('I') + sormtr, 1 warp per (b,o).
// ---------------------------------------------------------------------------
__global__ void __launch_bounds__(128) k3_eig(const float* __restrict__ bias,
                                              float* __restrict__ out) {
    __shared__ float shA[4][16][17];
    __shared__ float shZ[4][16][17];
    int w = threadIdx.x >> 5, lane = threadIdx.x & 31;
    int slot = blockIdx.x * 4 + w;               // b*32 + o
    float (*A)[17] = shA[w];
    float (*Z)[17] = shZ[w];
    const float* G = g_G + slot * 256;
    int lr = lane & 15;

    if (lane < 16) {
#pragma unroll
        for (int j = 0; j < 16; ++j) A[lane][j] = 0.5f * (G[lane * 16 + j] + G[j * 16 + lane]);
#pragma unroll
        for (int j = 0; j < 16; ++j) Z[lane][j] = (lane == j) ? 1.f : 0.f;
    }
    __syncwarp();

    float dreg = 0.f, ereg = 0.f, taureg = 0.f;

    // ---- ssytrd (UPLO='L', unblocked) ----
    for (int i = 0; i < 15; ++i) {
        float alpha = A[i + 1][i];
        float colv = (lane >= i + 2 && lane < 16) ? A[lane][i] : 0.f;
        float xnorm = sqrtf(wsum(colv * colv));
        float taui = 0.f, ei = alpha;
        if (i < 14 && xnorm != 0.f) {
            float beta = -copysignf(hypotf(alpha, xnorm), alpha);
            taui = (beta - alpha) / beta;
            float sc = 1.f / (alpha - beta);
            float vlane = colv * sc;
            if (lane == i + 1) vlane = 1.f;
            ei = beta;
            float xr = 0.f;
#pragma unroll
            for (int j = 0; j < 16; ++j) {
                float vj = sget(vlane, j);
                xr = fmaf(A[lr][j], vj, xr);
            }
            xr = (lane >= i + 1 && lane < 16) ? xr * taui : 0.f;
            float dotxv = wsum(xr * vlane);
            float wr = fmaf(-0.5f * taui * dotxv, vlane, xr);
            __syncwarp();
#pragma unroll
            for (int j = 0; j < 16; ++j) {
                float vj = sget(vlane, j), wj = sget(wr, j);
                if (lane >= j && lane < 16) {
                    float val = fmaf(wr, -vj, fmaf(vlane, -wj, A[lane][j]));
                    A[lane][j] = val;
                    if (lane != j) A[j][lane] = val;
                }
            }
            __syncwarp();
            if (lane >= i + 2 && lane < 16) A[lane][i] = vlane;
            __syncwarp();
        }
        SSET(ereg, i, ei);
        SSET(taureg, i, taui);
    }
    if (lane < 16) dreg = A[lane][lane];

    // ---- ssteqr (COMPZ='I') ----
    const float EPS  = 5.9604645e-08f;
    const float EPS2 = 3.5527137e-15f;
    const float SAFMIN = 1.17549435e-38f;
    const float SSFMAX = 3.0744573e18f;
    const float SSFMIN = 3.0517578e-05f;
    int l1 = 0, jtot = 0;
    const int nmaxit = 480;

    while (l1 <= 15) {
        if (l1 > 0) SSET(ereg, l1 - 1, 0.f);
        int m;
        {
            float dnext = __shfl_down_sync(FULLMASK, dreg, 1);
            float tst = fabsf(ereg);
            bool stop = (lane >= l1 && lane < 15) &&
                (tst == 0.f || tst <= (sqrtf(fabsf(dreg)) * sqrtf(fabsf(dnext))) * EPS);
            unsigned msk = __ballot_sync(FULLMASK, stop);
            m = msk ? (__ffs(msk) - 1) : 15;
            if (m < 15) SSET(ereg, m, 0.f);
        }
        int l = l1, lsv = l1, lend = m, lendsv = m;
        l1 = m + 1;
        if (lend == l) continue;
        float av = (lane >= l && lane <= lend && lane < 16) ? fabsf(dreg) : 0.f;
        float ae = (lane >= l && lane < lend) ? fabsf(ereg) : 0.f;
        float anorm = wmaxf(fmaxf(av, ae));
        if (anorm == 0.f) continue;
        int iscale = 0;
        if (anorm > SSFMAX) {
            iscale = 1; float sc = SSFMAX / anorm;
            if (lane >= l && lane <= lend) dreg *= sc;
            if (lane >= l && lane < lend)  ereg *= sc;
        } else if (anorm < SSFMIN) {
            iscale = 2; float sc = SSFMIN / anorm;
            if (lane >= l && lane <= lend) dreg *= sc;
            if (lane >= l && lane < lend)  ereg *= sc;
        }
        if (fabsf(sget(dreg, lend)) < fabsf(sget(dreg, l))) { int tmp = l; l = lend; lend = tmp; }

        if (lend > l) {
            // ---- QL sweeps ----
            for (;;) {
                int mq;
                {
                    float dnext = __shfl_down_sync(FULLMASK, dreg, 1);
                    bool stop = (lane >= l && lane < lend) &&
                        (ereg * ereg <= (EPS2 * fabsf(dreg)) * fabsf(dnext) + SAFMIN);
                    unsigned msk = __ballot_sync(FULLMASK, stop);
                    mq = msk ? (__ffs(msk) - 1) : lend;
                }
                if (mq < lend) SSET(ereg, mq, 0.f);
                float p = sget(dreg, l);
                if (mq == l) { l++; if (l <= lend) continue; break; }
                if (mq == l + 1) {
                    float rt1, rt2, cc, ss;
                    laev2(sget(dreg, l), sget(ereg, l), sget(dreg, l + 1), rt1, rt2, cc, ss);
                    if (lane < 16) {
                        float t = Z[lane][l + 1];
                        Z[lane][l + 1] = cc * t - ss * Z[lane][l];
                        Z[lane][l]     = ss * t + cc * Z[lane][l];
                    }
                    SSET(dreg, l, rt1); SSET(dreg, l + 1, rt2); SSET(ereg, l, 0.f);
                    l += 2; if (l <= lend) continue; break;
                }
                if (jtot >= nmaxit) break;
                jtot++;
                float el = sget(ereg, l);
                float gg = __fdividef(sget(dreg, l + 1) - p, 2.f * el);
                float rr = sqrtf(fmaf(gg, gg, 1.f));
                gg = sget(dreg, mq) - p + __fdividef(el, gg + copysignf(rr, gg));
                float ss = 1.f, cc = 1.f; p = 0.f;
                float carry = (lane < 16) ? Z[lane][mq] : 0.f;
                float dI1 = sget(dreg, mq);
                float eI  = sget(ereg, mq - 1);
                float dI  = sget(dreg, mq - 1);
                float zlo = (lane < 16) ? Z[lane][mq - 1] : 0.f;
                for (int i = mq - 1; i >= l; --i) {
                    int ip = (i - 1 >= l) ? i - 1 : l;      // clamped prefetch idx
                    float eN = sget(ereg, ip);
                    float dN = sget(dreg, ip);
                    float zN = (lane < 16 && i - 1 >= l) ? Z[lane][i - 1] : 0.f;
                    float ff = ss * eI, bb = cc * eI;
                    lartg(gg, ff, cc, ss, rr);
                    if (i != mq - 1) SSET(ereg, i + 1, rr);
                    gg = dI1 - p;
                    rr = (dI - gg) * ss + 2.f * cc * bb;
                    p = ss * rr;
                    SSET(dreg, i + 1, gg + p);
                    gg = cc * rr - bb;
                    if (lane < 16) {
                        Z[lane][i + 1] = fmaf(cc, carry, ss * zlo);
                        carry = fmaf(cc, zlo, -ss * carry);
                    }
                    dI1 = dI; dI = dN; eI = eN; zlo = zN;
                }
                if (lane < 16) Z[lane][l] = carry;
                SSET(dreg, l, sget(dreg, l) - p);
                SSET(ereg, l, gg);
            }
        } else {
            // ---- QR sweeps ----
            for (;;) {
                int mq;
                {
                    float dnext = __shfl_down_sync(FULLMASK, dreg, 1);
                    bool stop = (lane >= lend && lane < l) &&
                        (ereg * ereg <= (EPS2 * fabsf(dnext)) * fabsf(dreg) + SAFMIN);
                    unsigned msk = __ballot_sync(FULLMASK, stop);
                    mq = msk ? (31 - __clz(msk)) + 1 : lend;
                }
                if (mq > lend) SSET(ereg, mq - 1, 0.f);
                float p = sget(dreg, l);
                if (mq == l) { l--; if (l >= lend) continue; break; }
                if (mq == l - 1) {
                    float rt1, rt2, cc, ss;
                    laev2(sget(dreg, l - 1), sget(ereg, l - 1), sget(dreg, l), rt1, rt2, cc, ss);
                    if (lane < 16) {
                        float t = Z[lane][l];
                        Z[lane][l]     = cc * t - ss * Z[lane][l - 1];
                        Z[lane][l - 1] = ss * t + cc * Z[lane][l - 1];
                    }
                    SSET(dreg, l - 1, rt1); SSET(dreg, l, rt2); SSET(ereg, l - 1, 0.f);
                    l -= 2; if (l >= lend) continue; break;
                }
                if (jtot >= nmaxit) break;
                jtot++;
                float el = sget(ereg, l - 1);
                float gg = __fdividef(sget(dreg, l - 1) - p, 2.f * el);
                float rr = sqrtf(fmaf(gg, gg, 1.f));
                gg = sget(dreg, mq) - p + __fdividef(el, gg + copysignf(rr, gg));
                float ss = 1.f, cc = 1.f; p = 0.f;
                float carry = (lane < 16) ? Z[lane][mq] : 0.f;
                float dI  = sget(dreg, mq);
                float eI  = sget(ereg, mq);
                float dI1 = sget(dreg, mq + 1);
                float zhi = (lane < 16) ? Z[lane][mq + 1] : 0.f;
                for (int i = mq; i < l; ++i) {
                    int i2 = (i + 2 <= l) ? i + 2 : l;      // clamped prefetch idx
                    float eN  = sget(ereg, (i + 1 < l) ? i + 1 : l - 1);
                    float dN1 = sget(dreg, i2);
                    float zN  = (lane < 16 && i + 1 < l) ? Z[lane][i + 2] : 0.f;
                    float ff = ss * eI, bb = cc * eI;
                    lartg(gg, ff, cc, ss, rr);
                    if (i != mq) SSET(ereg, i - 1, rr);
                    gg = dI - p;
                    rr = (dI1 - gg) * ss + 2.f * cc * bb;
                    p = ss * rr;
                    SSET(dreg, i, gg + p);
                    gg = cc * rr - bb;
                    if (lane < 16) {
                        Z[lane][i] = fmaf(ss, zhi, cc * carry);
                        carry = fmaf(cc, zhi, -ss * carry);
                    }
                    dI = dI1; dI1 = dN1; eI = eN; zhi = zN;
                }
                if (lane < 16) Z[lane][l] = carry;
                SSET(dreg, l, sget(dreg, l) - p);
                SSET(ereg, l - 1, gg);
            }
        }
        if (iscale == 1) {
            float sc = anorm / SSFMAX;
            if (lane >= lsv && lane <= lendsv) dreg *= sc;
            if (lane >= lsv && lane < lendsv)  ereg *= sc;
        } else if (iscale == 2) {
            float sc = anorm / SSFMIN;
            if (lane >= lsv && lane <= lendsv) dreg *= sc;
            if (lane >= lsv && lane < lendsv)  ereg *= sc;
        }
    }

    // ---- sormtr: Z := H(1)...H(n-1) Z ----
    __syncwarp();
    for (int i = 14; i >= 0; --i) {
        float ti = sget(taureg, i);
        if (ti != 0.f) {
            float vlane = (lane == i + 1) ? 1.f
                        : ((lane >= i + 2 && lane < 16) ? A[lane][i] : 0.f);
            float wj = 0.f;
#pragma unroll
            for (int r = 0; r < 16; ++r) {
                float vr = sget(vlane, r);
                wj = fmaf(vr, Z[r][lr], wj);
            }
            wj *= ti;
            __syncwarp();
#pragma unroll
            for (int j = 0; j < 16; ++j) {
                float wjj = sget(wj, j);
                if (lane < 16) Z[lane][j] = fmaf(-vlane, wjj, Z[lane][j]);
            }
            __syncwarp();
        }
    }

    // ---- argmax eigenvalue, outputs ----
    float dv = (lane < 16) ? dreg : -3.4e38f;
    int idx = lane;
#pragma unroll
    for (int off = 16; off; off >>= 1) {
        float vo = __shfl_xor_sync(FULLMASK, dv, off);
        int io = __shfl_xor_sync(FULLMASK, idx, off);
        if (vo > dv || (vo == dv && io < idx)) { dv = vo; idx = io; }
    }
    int cmax = idx;
    float lam = sget(dreg, cmax);
    float tr = g_tr[slot];
    int o = slot & 31;
    if (lane == 0) out[slot] = 1.f / (1.f + expf(-(lam / tr - bias[o])));
    if (lane < 16) out[512 + slot * 16 + lane] = Z[lane][cmax];
}

// ---------------------------------------------------------------------------
extern "C" void kernel_launch(void* const* d_in, const int* in_sizes, int n_in,
                              void* d_out, int out_size) {
    const float* in   = (const float*)d_in[0];
    const float* wts  = (const float*)d_in[1];
    const float* bias = (const float*)d_in[2];
    float* out = (float*)d_out;
    k1a<<<2048, 256>>>(in);
    k1b<<<512, 256>>>();
    k2_gram<<<512, 256>>>(wts);
    k3_eig<<<128, 128>>>(bias, out);
}

// round 7
// speedup vs baseline: 1.6014x; 1.0071x over previous
// SpectralCapsules R7: k3 single-column sormtr + sqrt-slarfg + 1-warp blocks;
// k1b fused into k2; k1a unchanged.
#include <cuda_runtime.h>
#include <math.h>

#define FULLMASK 0xffffffffu

constexpr int Bb = 16;    // batch
constexpr int Mm = 256;   // H*W
constexpr int Cc = 544;   // channels = L*(P+1)

__device__ float g_Sp[Bb * 32 * 4 * 256]; // partial S per m-chunk
__device__ float g_G[Bb * 32 * 256];      // G[b][o][16][16]
__device__ float g_tr[Bb * 32];

// ---------------------------------------------------------------------------
// K1a: partial S over 64 m per block (unchanged R6).
// ---------------------------------------------------------------------------
__global__ void __launch_bounds__(256) k1a(const float* __restrict__ in) {
    int blk = blockIdx.x;               // ((b*32+l)*4 + chunk)
    int chunk = blk & 3;
    int bl = blk >> 2;
    int b = bl >> 5, l = bl & 31;
    __shared__ float sp[64 * 16];
    __shared__ float sa2[64];
    int t = threadIdx.x;
    const float* base = in + (size_t)b * Mm * Cc + (size_t)chunk * 64 * Cc;
    {
        int mm = t >> 2, q = t & 3;
        const float4* src = (const float4*)(base + (size_t)mm * Cc + l * 16) + q;
        ((float4*)sp)[mm * 4 + q] = *src;
    }
    if (t < 64) {
        float a = base[(size_t)t * Cc + 512 + l];
        sa2[t] = a * a;
    }
    __syncthreads();
    int r = t >> 4, c = t & 15;
    float acc = 0.f;
#pragma unroll
    for (int mm = 0; mm < 64; ++mm)
        acc = fmaf(sa2[mm] * sp[mm * 16 + r], sp[mm * 16 + c], acc);
    g_Sp[blk * 256 + t] = acc;
}

// ---------------------------------------------------------------------------
// K2: G[b,o] = sum_l (I4 (x) W^T) S[b,l] (I4 (x) W); trace. S assembled from
// the 4 partials inline, fixed order ((p0+p1)+p2)+p3 == former k1b.
// ---------------------------------------------------------------------------
__global__ void k2_gram(const float* __restrict__ wts) {
    int blk = blockIdx.x;          // b*32 + o
    int b = blk >> 5, o = blk & 31;
    __shared__ float sS[256];
    __shared__ float sH[256];
    __shared__ float sW[512];
    int t = threadIdx.x;
    int r = t >> 4, c = t & 15;
    int i = r >> 2, k = r & 3;
    int cb = c & ~3, km = c & 3;
    sW[t]       = wts[(((t >> 4)     ) * 32 + o) * 16 + (t & 15)];
    sW[t + 256] = wts[(((t >> 4) + 16) * 32 + o) * 16 + (t & 15)];
    const float* p0 = g_Sp + (size_t)(b * 32) * 1024 + t;
    float pre = ((p0[0] + p0[256]) + p0[512]) + p0[768];
    float g = 0.f;
    for (int l = 0; l < 32; ++l) {
        sS[t] = pre;
        __syncthreads();
        if (l < 31) {
            const float* pn = g_Sp + (size_t)(b * 32 + l + 1) * 1024 + t;
            pre = ((pn[0] + pn[256]) + pn[512]) + pn[768];
        }
        const float* wv = &sW[l * 16];
        float h = 0.f;
#pragma unroll
        for (int j = 0; j < 4; ++j) h = fmaf(sS[r * 16 + cb + j], wv[j * 4 + km], h);
        sH[t] = h;
        __syncthreads();
#pragma unroll
        for (int j = 0; j < 4; ++j) g = fmaf(wv[j * 4 + k], sH[(i * 4 + j) * 16 + c], g);
    }
    g_G[blk * 256 + t] = g;
    __syncthreads();
    if (r == c) sS[r] = g;
    __syncthreads();
    if (t == 0) {
        float tr = 0.f;
#pragma unroll
        for (int p2 = 0; p2 < 16; ++p2) tr += sS[p2];
        g_tr[blk] = tr;
    }
}

// ---------------------------------------------------------------------------
// K3 helpers
// ---------------------------------------------------------------------------
__device__ __forceinline__ float wsum(float x) {
#pragma unroll
    for (int o = 16; o; o >>= 1) x += __shfl_xor_sync(FULLMASK, x, o);
    return x;
}
__device__ __forceinline__ float wmaxf(float x) {
#pragma unroll
    for (int o = 16; o; o >>= 1) x = fmaxf(x, __shfl_xor_sync(FULLMASK, x, o));
    return x;
}
__device__ __forceinline__ float sget(float v, int i) {
    return __shfl_sync(FULLMASK, v, i);
}
#define SSET(var, idx, val) do { float _v = (val); int _i = (idx); \
    if ((threadIdx.x & 31) == _i) var = _v; } while (0)

// lartg fast path via rsqrt
__device__ __forceinline__ void lartg(float f, float g, float& c, float& s, float& r) {
    if (g == 0.f)      { c = 1.f; s = 0.f; r = f; }
    else if (f == 0.f) { c = 0.f; s = copysignf(1.f, g); r = fabsf(g); }
    else {
        float t2 = fmaf(f, f, g * g);
        float rinv = rsqrtf(t2);
        float d = t2 * rinv;
        c = fabsf(f) * rinv;
        r = copysignf(d, f);
        s = g * rinv * copysignf(1.f, f);
    }
}

// LAPACK slaev2 (rare path: keep precise arithmetic)
__device__ __forceinline__ void laev2(float a, float b, float c,
                                      float& rt1, float& rt2, float& cs1, float& sn1) {
    float sm = a + c, df = a - c;
    float adf = fabsf(df);
    float tb = b + b;
    float ab = fabsf(tb);
    float acmx, acmn;
    if (fabsf(a) > fabsf(c)) { acmx = a; acmn = c; } else { acmx = c; acmn = a; }
    float rt;
    if (adf > ab)      rt = adf * sqrtf(1.f + (ab / adf) * (ab / adf));
    else if (adf < ab) rt = ab * sqrtf(1.f + (adf / ab) * (adf / ab));
    else               rt = ab * sqrtf(2.f);
    int sgn1;
    if (sm < 0.f)      { rt1 = 0.5f * (sm - rt); sgn1 = -1; rt2 = (acmx / rt1) * acmn - (b / rt1) * b; }
    else if (sm > 0.f) { rt1 = 0.5f * (sm + rt); sgn1 = 1;  rt2 = (acmx / rt1) * acmn - (b / rt1) * b; }
    else               { rt1 = 0.5f * rt; rt2 = -0.5f * rt; sgn1 = 1; }
    float cs; int sgn2;
    if (df >= 0.f) { cs = df + rt; sgn2 = 1; } else { cs = df - rt; sgn2 = -1; }
    float acs = fabsf(cs);
    if (acs > ab) {
        float ct = -tb / cs;
        sn1 = 1.f / sqrtf(1.f + ct * ct);
        cs1 = ct * sn1;
    } else {
        if (ab == 0.f) { cs1 = 1.f; sn1 = 0.f; }
        else {
            float tn = -cs / tb;
            cs1 = 1.f / sqrtf(1.f + tn * tn);
            sn1 = tn * cs1;
        }
    }
    if (sgn1 == sgn2) { float tn = cs1; cs1 = -sn1; sn1 = tn; }
}

// ---------------------------------------------------------------------------
// K3: ssytrd('L') + ssteqr('I') + single-column sormtr; 1 warp per block.
// ---------------------------------------------------------------------------
__global__ void __launch_bounds__(32) k3_eig(const float* __restrict__ bias,
                                             float* __restrict__ out) {
    __shared__ float A[16][17];
    __shared__ float Z[16][17];
    int lane = threadIdx.x & 31;
    int slot = blockIdx.x;                       // b*32 + o
    const float* G = g_G + slot * 256;
    int lr = lane & 15;

    if (lane < 16) {
#pragma unroll
        for (int j = 0; j < 16; ++j) A[lane][j] = 0.5f * (G[lane * 16 + j] + G[j * 16 + lane]);
#pragma unroll
        for (int j = 0; j < 16; ++j) Z[lane][j] = (lane == j) ? 1.f : 0.f;
    }
    __syncwarp();

    float dreg = 0.f, ereg = 0.f, taureg = 0.f;

    // ---- ssytrd (UPLO='L', unblocked) ----
    for (int i = 0; i < 15; ++i) {
        float alpha = A[i + 1][i];
        float colv = (lane >= i + 2 && lane < 16) ? A[lane][i] : 0.f;
        float xnorm = sqrtf(wsum(colv * colv));
        float taui = 0.f, ei = alpha;
        if (i < 14 && xnorm != 0.f) {
            float beta = -copysignf(sqrtf(fmaf(alpha, alpha, xnorm * xnorm)), alpha);
            taui = __fdividef(beta - alpha, beta);
            float sc = __fdividef(1.f, alpha - beta);
            float vlane = colv * sc;
            if (lane == i + 1) vlane = 1.f;
            ei = beta;
            float xr = 0.f;
#pragma unroll
            for (int j = 0; j < 16; ++j) {
                float vj = sget(vlane, j);
                xr = fmaf(A[lr][j], vj, xr);
            }
            xr = (lane >= i + 1 && lane < 16) ? xr * taui : 0.f;
            float dotxv = wsum(xr * vlane);
            float wr = fmaf(-0.5f * taui * dotxv, vlane, xr);
            __syncwarp();
#pragma unroll
            for (int j = 0; j < 16; ++j) {
                float vj = sget(vlane, j), wj = sget(wr, j);
                if (lane >= j && lane < 16) {
                    float val = fmaf(wr, -vj, fmaf(vlane, -wj, A[lane][j]));
                    A[lane][j] = val;
                    if (lane != j) A[j][lane] = val;
                }
            }
            __syncwarp();
            if (lane >= i + 2 && lane < 16) A[lane][i] = vlane;
            __syncwarp();
        }
        SSET(ereg, i, ei);
        SSET(taureg, i, taui);
    }
    if (lane < 16) dreg = A[lane][lane];

    // ---- ssteqr (COMPZ='I') ----
    const float EPS  = 5.9604645e-08f;
    const float EPS2 = 3.5527137e-15f;
    const float SAFMIN = 1.17549435e-38f;
    const float SSFMAX = 3.0744573e18f;
    const float SSFMIN = 3.0517578e-05f;
    int l1 = 0, jtot = 0;
    const int nmaxit = 480;

    while (l1 <= 15) {
        if (l1 > 0) SSET(ereg, l1 - 1, 0.f);
        int m;
        {
            float dnext = __shfl_down_sync(FULLMASK, dreg, 1);
            float tst = fabsf(ereg);
            bool stop = (lane >= l1 && lane < 15) &&
                (tst == 0.f || tst <= (sqrtf(fabsf(dreg)) * sqrtf(fabsf(dnext))) * EPS);
            unsigned msk = __ballot_sync(FULLMASK, stop);
            m = msk ? (__ffs(msk) - 1) : 15;
            if (m < 15) SSET(ereg, m, 0.f);
        }
        int l = l1, lsv = l1, lend = m, lendsv = m;
        l1 = m + 1;
        if (lend == l) continue;
        float av = (lane >= l && lane <= lend && lane < 16) ? fabsf(dreg) : 0.f;
        float ae = (lane >= l && lane < lend) ? fabsf(ereg) : 0.f;
        float anorm = wmaxf(fmaxf(av, ae));
        if (anorm == 0.f) continue;
        int iscale = 0;
        if (anorm > SSFMAX) {
            iscale = 1; float sc = SSFMAX / anorm;
            if (lane >= l && lane <= lend) dreg *= sc;
            if (lane >= l && lane < lend)  ereg *= sc;
        } else if (anorm < SSFMIN) {
            iscale = 2; float sc = SSFMIN / anorm;
            if (lane >= l && lane <= lend) dreg *= sc;
            if (lane >= l && lane < lend)  ereg *= sc;
        }
        if (fabsf(sget(dreg, lend)) < fabsf(sget(dreg, l))) { int tmp = l; l = lend; lend = tmp; }

        if (lend > l) {
            // ---- QL sweeps ----
            for (;;) {
                int mq;
                {
                    float dnext = __shfl_down_sync(FULLMASK, dreg, 1);
                    bool stop = (lane >= l && lane < lend) &&
                        (ereg * ereg <= (EPS2 * fabsf(dreg)) * fabsf(dnext) + SAFMIN);
                    unsigned msk = __ballot_sync(FULLMASK, stop);
                    mq = msk ? (__ffs(msk) - 1) : lend;
                }
                if (mq < lend) SSET(ereg, mq, 0.f);
                float p = sget(dreg, l);
                if (mq == l) { l++; if (l <= lend) continue; break; }
                if (mq == l + 1) {
                    float rt1, rt2, cc, ss;
                    laev2(sget(dreg, l), sget(ereg, l), sget(dreg, l + 1), rt1, rt2, cc, ss);
                    if (lane < 16) {
                        float t = Z[lane][l + 1];
                        Z[lane][l + 1] = cc * t - ss * Z[lane][l];
                        Z[lane][l]     = ss * t + cc * Z[lane][l];
                    }
                    SSET(dreg, l, rt1); SSET(dreg, l + 1, rt2); SSET(ereg, l, 0.f);
                    l += 2; if (l <= lend) continue; break;
                }
                if (jtot >= nmaxit) break;
                jtot++;
                float el = sget(ereg, l);
                float gg = __fdividef(sget(dreg, l + 1) - p, 2.f * el);
                float rr = sqrtf(fmaf(gg, gg, 1.f));
                gg = sget(dreg, mq) - p + __fdividef(el, gg + copysignf(rr, gg));
                float ss = 1.f, cc = 1.f; p = 0.f;
                float carry = (lane < 16) ? Z[lane][mq] : 0.f;
                float dI1 = sget(dreg, mq);
                float eI  = sget(ereg, mq - 1);
                float dI  = sget(dreg, mq - 1);
                float zlo = (lane < 16) ? Z[lane][mq - 1] : 0.f;
                for (int i = mq - 1; i >= l; --i) {
                    int ip = (i - 1 >= l) ? i - 1 : l;
                    float eN = sget(ereg, ip);
                    float dN = sget(dreg, ip);
                    float zN = (lane < 16 && i - 1 >= l) ? Z[lane][i - 1] : 0.f;
                    float ff = ss * eI, bb = cc * eI;
                    lartg(gg, ff, cc, ss, rr);
                    if (i != mq - 1) SSET(ereg, i + 1, rr);
                    gg = dI1 - p;
                    rr = (dI - gg) * ss + 2.f * cc * bb;
                    p = ss * rr;
                    SSET(dreg, i + 1, gg + p);
                    gg = cc * rr - bb;
                    if (lane < 16) {
                        Z[lane][i + 1] = fmaf(cc, carry, ss * zlo);
                        carry = fmaf(cc, zlo, -ss * carry);
                    }
                    dI1 = dI; dI = dN; eI = eN; zlo = zN;
                }
                if (lane < 16) Z[lane][l] = carry;
                SSET(dreg, l, sget(dreg, l) - p);
                SSET(ereg, l, gg);
            }
        } else {
            // ---- QR sweeps ----
            for (;;) {
                int mq;
                {
                    float dnext = __shfl_down_sync(FULLMASK, dreg, 1);
                    bool stop = (lane >= lend && lane < l) &&
                        (ereg * ereg <= (EPS2 * fabsf(dnext)) * fabsf(dreg) + SAFMIN);
                    unsigned msk = __ballot_sync(FULLMASK, stop);
                    mq = msk ? (31 - __clz(msk)) + 1 : lend;
                }
                if (mq > lend) SSET(ereg, mq - 1, 0.f);
                float p = sget(dreg, l);
                if (mq == l) { l--; if (l >= lend) continue; break; }
                if (mq == l - 1) {
                    float rt1, rt2, cc, ss;
                    laev2(sget(dreg, l - 1), sget(ereg, l - 1), sget(dreg, l), rt1, rt2, cc, ss);
                    if (lane < 16) {
                        float t = Z[lane][l];
                        Z[lane][l]     = cc * t - ss * Z[lane][l - 1];
                        Z[lane][l - 1] = ss * t + cc * Z[lane][l - 1];
                    }
                    SSET(dreg, l - 1, rt1); SSET(dreg, l, rt2); SSET(ereg, l - 1, 0.f);
                    l -= 2; if (l >= lend) continue; break;
                }
                if (jtot >= nmaxit) break;
                jtot++;
                float el = sget(ereg, l - 1);
                float gg = __fdividef(sget(dreg, l - 1) - p, 2.f * el);
                float rr = sqrtf(fmaf(gg, gg, 1.f));
                gg = sget(dreg, mq) - p + __fdividef(el, gg + copysignf(rr, gg));
                float ss = 1.f, cc = 1.f; p = 0.f;
                float carry = (lane < 16) ? Z[lane][mq] : 0.f;
                float dI  = sget(dreg, mq);
                float eI  = sget(ereg, mq);
                float dI1 = sget(dreg, mq + 1);
                float zhi = (lane < 16) ? Z[lane][mq + 1] : 0.f;
                for (int i = mq; i < l; ++i) {
                    int i2 = (i + 2 <= l) ? i + 2 : l;
                    float eN  = sget(ereg, (i + 1 < l) ? i + 1 : l - 1);
                    float dN1 = sget(dreg, i2);
                    float zN  = (lane < 16 && i + 1 < l) ? Z[lane][i + 2] : 0.f;
                    float ff = ss * eI, bb = cc * eI;
                    lartg(gg, ff, cc, ss, rr);
                    if (i != mq) SSET(ereg, i - 1, rr);
                    gg = dI - p;
                    rr = (dI1 - gg) * ss + 2.f * cc * bb;
                    p = ss * rr;
                    SSET(dreg, i, gg + p);
                    gg = cc * rr - bb;
                    if (lane < 16) {
                        Z[lane][i] = fmaf(ss, zhi, cc * carry);
                        carry = fmaf(cc, zhi, -ss * carry);
                    }
                    dI = dI1; dI1 = dN1; eI = eN; zhi = zN;
                }
                if (lane < 16) Z[lane][l] = carry;
                SSET(dreg, l, sget(dreg, l) - p);
                SSET(ereg, l - 1, gg);
            }
        }
        if (iscale == 1) {
            float sc = anorm / SSFMAX;
            if (lane >= lsv && lane <= lendsv) dreg *= sc;
            if (lane >= lsv && lane < lendsv)  ereg *= sc;
        } else if (iscale == 2) {
            float sc = anorm / SSFMIN;
            if (lane >= lsv && lane <= lendsv) dreg *= sc;
            if (lane >= lsv && lane < lendsv)  ereg *= sc;
        }
    }

    // ---- argmax eigenvalue BEFORE back-transform ----
    float dv = (lane < 16) ? dreg : -3.4e38f;
    int idx = lane;
#pragma unroll
    for (int off = 16; off; off >>= 1) {
        float vo = __shfl_xor_sync(FULLMASK, dv, off);
        int io = __shfl_xor_sync(FULLMASK, idx, off);
        if (vo > dv || (vo == dv && io < idx)) { dv = vo; idx = io; }
    }
    int cmax = idx;
    float lam = sget(dreg, cmax);

    // ---- sormtr on the single needed column: v := H(1)...H(n-1) Z[:,cmax].
    // LAPACK applies each H independently per column -> identical arithmetic.
    float v16 = (lane < 16) ? Z[lane][cmax] : 0.f;
    for (int i = 14; i >= 0; --i) {
        float ti = sget(taureg, i);
        if (ti != 0.f) {
            float vlane = (lane == i + 1) ? 1.f
                        : ((lane >= i + 2 && lane < 16) ? A[lane][i] : 0.f);
            float wj = wsum(vlane * v16) * ti;
            v16 = fmaf(-vlane, wj, v16);
        }
    }

    float tr = g_tr[slot];
    int o = slot & 31;
    if (lane == 0) out[slot] = 1.f / (1.f + expf(-(lam / tr - bias[o])));
    if (lane < 16) out[512 + slot * 16 + lane] = v16;
}

// ---------------------------------------------------------------------------
extern "C" void kernel_launch(void* const* d_in, const int* in_sizes, int n_in,
                              void* d_out, int out_size) {
    const float* in   = (const float*)d_in[0];
    const float* wts  = (const float*)d_in[1];
    const float* bias = (const float*)d_in[2];
    float* out = (float*)d_out;
    k1a<<<2048, 256>>>(in);
    k2_gram<<<512, 256>>>(wts);
    k3_eig<<<512, 32>>>(bias, out);
}

// round 8
// speedup vs baseline: 1.6978x; 1.0602x over previous
// SpectralCapsules R8: k1a 2x2 register tiling + float2 LDS (LDS-bw bound fix);
// k2/k3 unchanged from R7 (isolate the delta).
#include <cuda_runtime.h>
#include <math.h>

#define FULLMASK 0xffffffffu

constexpr int Bb = 16;    // batch
constexpr int Mm = 256;   // H*W
constexpr int Cc = 544;   // channels = L*(P+1)

__device__ float g_Sp[Bb * 32 * 4 * 256]; // partial S per m-chunk
__device__ float g_G[Bb * 32 * 256];      // G[b][o][16][16]
__device__ float g_tr[Bb * 32];

// ---------------------------------------------------------------------------
// K1a: partial S over 64 m per block. 2x2 tile per thread, 4 m-groups of 16,
// fixed-order group reduction. 3 LDS per 4 FMA-pairs (was 8).
// ---------------------------------------------------------------------------
__global__ void __launch_bounds__(256) k1a(const float* __restrict__ in) {
    int blk = blockIdx.x;               // ((b*32+l)*4 + chunk)
    int chunk = blk & 3;
    int bl = blk >> 2;
    int b = bl >> 5, l = bl & 31;
    __shared__ float sp[64 * 16];
    __shared__ float sa2[64];
    __shared__ float red[4][16 * 17];   // padded rows (stride 17)
    int t = threadIdx.x;
    const float* base = in + (size_t)b * Mm * Cc + (size_t)chunk * 64 * Cc;
    {
        int mm = t >> 2, q = t & 3;
        const float4* src = (const float4*)(base + (size_t)mm * Cc + l * 16) + q;
        ((float4*)sp)[mm * 4 + q] = *src;
    }
    if (t < 64) {
        float a = base[(size_t)t * Cc + 512 + l];
        sa2[t] = a * a;
    }
    __syncthreads();
    int g = t >> 6, u = t & 63;
    int r0 = (u >> 3) * 2, c0 = (u & 7) * 2;
    float a00 = 0.f, a01 = 0.f, a10 = 0.f, a11 = 0.f;
#pragma unroll
    for (int mm = 0; mm < 16; ++mm) {
        int m = g * 16 + mm;
        float a2 = sa2[m];
        float2 vr = *(const float2*)&sp[m * 16 + r0];
        float2 vc = *(const float2*)&sp[m * 16 + c0];
        float t0 = a2 * vr.x, t1 = a2 * vr.y;
        a00 = fmaf(t0, vc.x, a00);
        a01 = fmaf(t0, vc.y, a01);
        a10 = fmaf(t1, vc.x, a10);
        a11 = fmaf(t1, vc.y, a11);
    }
    red[g][r0 * 17 + c0]           = a00;
    red[g][r0 * 17 + c0 + 1]       = a01;
    red[g][(r0 + 1) * 17 + c0]     = a10;
    red[g][(r0 + 1) * 17 + c0 + 1] = a11;
    __syncthreads();
    {
        int r = t >> 4, c = t & 15;
        int idx = r * 17 + c;
        g_Sp[blk * 256 + t] = ((red[0][idx] + red[1][idx]) + red[2][idx]) + red[3][idx];
    }
}

// ---------------------------------------------------------------------------
// K2: G[b,o] = sum_l (I4 (x) W^T) S[b,l] (I4 (x) W); trace. S assembled from
// the 4 partials inline, fixed order ((p0+p1)+p2)+p3.
// ---------------------------------------------------------------------------
__global__ void k2_gram(const float* __restrict__ wts) {
    int blk = blockIdx.x;          // b*32 + o
    int b = blk >> 5, o = blk & 31;
    __shared__ float sS[256];
    __shared__ float sH[256];
    __shared__ float sW[512];
    int t = threadIdx.x;
    int r = t >> 4, c = t & 15;
    int i = r >> 2, k = r & 3;
    int cb = c & ~3, km = c & 3;
    sW[t]       = wts[(((t >> 4)     ) * 32 + o) * 16 + (t & 15)];
    sW[t + 256] = wts[(((t >> 4) + 16) * 32 + o) * 16 + (t & 15)];
    const float* p0 = g_Sp + (size_t)(b * 32) * 1024 + t;
    float pre = ((p0[0] + p0[256]) + p0[512]) + p0[768];
    float g = 0.f;
    for (int l = 0; l < 32; ++l) {
        sS[t] = pre;
        __syncthreads();
        if (l < 31) {
            const float* pn = g_Sp + (size_t)(b * 32 + l + 1) * 1024 + t;
            pre = ((pn[0] + pn[256]) + pn[512]) + pn[768];
        }
        const float* wv = &sW[l * 16];
        float h = 0.f;
#pragma unroll
        for (int j = 0; j < 4; ++j) h = fmaf(sS[r * 16 + cb + j], wv[j * 4 + km], h);
        sH[t] = h;
        __syncthreads();
#pragma unroll
        for (int j = 0; j < 4; ++j) g = fmaf(wv[j * 4 + k], sH[(i * 4 + j) * 16 + c], g);
    }
    g_G[blk * 256 + t] = g;
    __syncthreads();
    if (r == c) sS[r] = g;
    __syncthreads();
    if (t == 0) {
        float tr = 0.f;
#pragma unroll
        for (int p2 = 0; p2 < 16; ++p2) tr += sS[p2];
        g_tr[blk] = tr;
    }
}

// ---------------------------------------------------------------------------
// K3 helpers
// ---------------------------------------------------------------------------
__device__ __forceinline__ float wsum(float x) {
#pragma unroll
    for (int o = 16; o; o >>= 1) x += __shfl_xor_sync(FULLMASK, x, o);
    return x;
}
__device__ __forceinline__ float wmaxf(float x) {
#pragma unroll
    for (int o = 16; o; o >>= 1) x = fmaxf(x, __shfl_xor_sync(FULLMASK, x, o));
    return x;
}
__device__ __forceinline__ float sget(float v, int i) {
    return __shfl_sync(FULLMASK, v, i);
}
#define SSET(var, idx, val) do { float _v = (val); int _i = (idx); \
    if ((threadIdx.x & 31) == _i) var = _v; } while (0)

// lartg fast path via rsqrt
__device__ __forceinline__ void lartg(float f, float g, float& c, float& s, float& r) {
    if (g == 0.f)      { c = 1.f; s = 0.f; r = f; }
    else if (f == 0.f) { c = 0.f; s = copysignf(1.f, g); r = fabsf(g); }
    else {
        float t2 = fmaf(f, f, g * g);
        float rinv = rsqrtf(t2);
        float d = t2 * rinv;
        c = fabsf(f) * rinv;
        r = copysignf(d, f);
        s = g * rinv * copysignf(1.f, f);
    }
}

// LAPACK slaev2 (rare path: keep precise arithmetic)
__device__ __forceinline__ void laev2(float a, float b, float c,
                                      float& rt1, float& rt2, float& cs1, float& sn1) {
    float sm = a + c, df = a - c;
    float adf = fabsf(df);
    float tb = b + b;
    float ab = fabsf(tb);
    float acmx, acmn;
    if (fabsf(a) > fabsf(c)) { acmx = a; acmn = c; } else { acmx = c; acmn = a; }
    float rt;
    if (adf > ab)      rt = adf * sqrtf(1.f + (ab / adf) * (ab / adf));
    else if (adf < ab) rt = ab * sqrtf(1.f + (adf / ab) * (adf / ab));
    else               rt = ab * sqrtf(2.f);
    int sgn1;
    if (sm < 0.f)      { rt1 = 0.5f * (sm - rt); sgn1 = -1; rt2 = (acmx / rt1) * acmn - (b / rt1) * b; }
    else if (sm > 0.f) { rt1 = 0.5f * (sm + rt); sgn1 = 1;  rt2 = (acmx / rt1) * acmn - (b / rt1) * b; }
    else               { rt1 = 0.5f * rt; rt2 = -0.5f * rt; sgn1 = 1; }
    float cs; int sgn2;
    if (df >= 0.f) { cs = df + rt; sgn2 = 1; } else { cs = df - rt; sgn2 = -1; }
    float acs = fabsf(cs);
    if (acs > ab) {
        float ct = -tb / cs;
        sn1 = 1.f / sqrtf(1.f + ct * ct);
        cs1 = ct * sn1;
    } else {
        if (ab == 0.f) { cs1 = 1.f; sn1 = 0.f; }
        else {
            float tn = -cs / tb;
            cs1 = 1.f / sqrtf(1.f + tn * tn);
            sn1 = tn * cs1;
        }
    }
    if (sgn1 == sgn2) { float tn = cs1; cs1 = -sn1; sn1 = tn; }
}

// ---------------------------------------------------------------------------
// K3: ssytrd('L') + ssteqr('I') + single-column sormtr; 1 warp per block.
// ---------------------------------------------------------------------------
__global__ void __launch_bounds__(32) k3_eig(const float* __restrict__ bias,
                                             float* __restrict__ out) {
    __shared__ float A[16][17];
    __shared__ float Z[16][17];
    int lane = threadIdx.x & 31;
    int slot = blockIdx.x;                       // b*32 + o
    const float* G = g_G + slot * 256;
    int lr = lane & 15;

    if (lane < 16) {
#pragma unroll
        for (int j = 0; j < 16; ++j) A[lane][j] = 0.5f * (G[lane * 16 + j] + G[j * 16 + lane]);
#pragma unroll
        for (int j = 0; j < 16; ++j) Z[lane][j] = (lane == j) ? 1.f : 0.f;
    }
    __syncwarp();

    float dreg = 0.f, ereg = 0.f, taureg = 0.f;

    // ---- ssytrd (UPLO='L', unblocked) ----
    for (int i = 0; i < 15; ++i) {
        float alpha = A[i + 1][i];
        float colv = (lane >= i + 2 && lane < 16) ? A[lane][i] : 0.f;
        float xnorm = sqrtf(wsum(colv * colv));
        float taui = 0.f, ei = alpha;
        if (i < 14 && xnorm != 0.f) {
            float beta = -copysignf(sqrtf(fmaf(alpha, alpha, xnorm * xnorm)), alpha);
            taui = __fdividef(beta - alpha, beta);
            float sc = __fdividef(1.f, alpha - beta);
            float vlane = colv * sc;
            if (lane == i + 1) vlane = 1.f;
            ei = beta;
            float xr = 0.f;
#pragma unroll
            for (int j = 0; j < 16; ++j) {
                float vj = sget(vlane, j);
                xr = fmaf(A[lr][j], vj, xr);
            }
            xr = (lane >= i + 1 && lane < 16) ? xr * taui : 0.f;
            float dotxv = wsum(xr * vlane);
            float wr = fmaf(-0.5f * taui * dotxv, vlane, xr);
            __syncwarp();
#pragma unroll
            for (int j = 0; j < 16; ++j) {
                float vj = sget(vlane, j), wj = sget(wr, j);
                if (lane >= j && lane < 16) {
                    float val = fmaf(wr, -vj, fmaf(vlane, -wj, A[lane][j]));
                    A[lane][j] = val;
                    if (lane != j) A[j][lane] = val;
                }
            }
            __syncwarp();
            if (lane >= i + 2 && lane < 16) A[lane][i] = vlane;
            __syncwarp();
        }
        SSET(ereg, i, ei);
        SSET(taureg, i, taui);
    }
    if (lane < 16) dreg = A[lane][lane];

    // ---- ssteqr (COMPZ='I') ----
    const float EPS  = 5.9604645e-08f;
    const float EPS2 = 3.5527137e-15f;
    const float SAFMIN = 1.17549435e-38f;
    const float SSFMAX = 3.0744573e18f;
    const float SSFMIN = 3.0517578e-05f;
    int l1 = 0, jtot = 0;
    const int nmaxit = 480;

    while (l1 <= 15) {
        if (l1 > 0) SSET(ereg, l1 - 1, 0.f);
        int m;
        {
            float dnext = __shfl_down_sync(FULLMASK, dreg, 1);
            float tst = fabsf(ereg);
            bool stop = (lane >= l1 && lane < 15) &&
                (tst == 0.f || tst <= (sqrtf(fabsf(dreg)) * sqrtf(fabsf(dnext))) * EPS);
            unsigned msk = __ballot_sync(FULLMASK, stop);
            m = msk ? (__ffs(msk) - 1) : 15;
            if (m < 15) SSET(ereg, m, 0.f);
        }
        int l = l1, lsv = l1, lend = m, lendsv = m;
        l1 = m + 1;
        if (lend == l) continue;
        float av = (lane >= l && lane <= lend && lane < 16) ? fabsf(dreg) : 0.f;
        float ae = (lane >= l && lane < lend) ? fabsf(ereg) : 0.f;
        float anorm = wmaxf(fmaxf(av, ae));
        if (anorm == 0.f) continue;
        int iscale = 0;
        if (anorm > SSFMAX) {
            iscale = 1; float sc = SSFMAX / anorm;
            if (lane >= l && lane <= lend) dreg *= sc;
            if (lane >= l && lane < lend)  ereg *= sc;
        } else if (anorm < SSFMIN) {
            iscale = 2; float sc = SSFMIN / anorm;
            if (lane >= l && lane <= lend) dreg *= sc;
            if (lane >= l && lane < lend)  ereg *= sc;
        }
        if (fabsf(sget(dreg, lend)) < fabsf(sget(dreg, l))) { int tmp = l; l = lend; lend = tmp; }

        if (lend > l) {
            // ---- QL sweeps ----
            for (;;) {
                int mq;
                {
                    float dnext = __shfl_down_sync(FULLMASK, dreg, 1);
                    bool stop = (lane >= l && lane < lend) &&
                        (ereg * ereg <= (EPS2 * fabsf(dreg)) * fabsf(dnext) + SAFMIN);
                    unsigned msk = __ballot_sync(FULLMASK, stop);
                    mq = msk ? (__ffs(msk) - 1) : lend;
                }
                if (mq < lend) SSET(ereg, mq, 0.f);
                float p = sget(dreg, l);
                if (mq == l) { l++; if (l <= lend) continue; break; }
                if (mq == l + 1) {
                    float rt1, rt2, cc, ss;
                    laev2(sget(dreg, l), sget(ereg, l), sget(dreg, l + 1), rt1, rt2, cc, ss);
                    if (lane < 16) {
                        float t = Z[lane][l + 1];
                        Z[lane][l + 1] = cc * t - ss * Z[lane][l];
                        Z[lane][l]     = ss * t + cc * Z[lane][l];
                    }
                    SSET(dreg, l, rt1); SSET(dreg, l + 1, rt2); SSET(ereg, l, 0.f);
                    l += 2; if (l <= lend) continue; break;
                }
                if (jtot >= nmaxit) break;
                jtot++;
                float el = sget(ereg, l);
                float gg = __fdividef(sget(dreg, l + 1) - p, 2.f * el);
                float rr = sqrtf(fmaf(gg, gg, 1.f));
                gg = sget(dreg, mq) - p + __fdividef(el, gg + copysignf(rr, gg));
                float ss = 1.f, cc = 1.f; p = 0.f;
                float carry = (lane < 16) ? Z[lane][mq] : 0.f;
                float dI1 = sget(dreg, mq);
                float eI  = sget(ereg, mq - 1);
                float dI  = sget(dreg, mq - 1);
                float zlo = (lane < 16) ? Z[lane][mq - 1] : 0.f;
                for (int i = mq - 1; i >= l; --i) {
                    int ip = (i - 1 >= l) ? i - 1 : l;
                    float eN = sget(ereg, ip);
                    float dN = sget(dreg, ip);
                    float zN = (lane < 16 && i - 1 >= l) ? Z[lane][i - 1] : 0.f;
                    float ff = ss * eI, bb = cc * eI;
                    lartg(gg, ff, cc, ss, rr);
                    if (i != mq - 1) SSET(ereg, i + 1, rr);
                    gg = dI1 - p;
                    rr = (dI - gg) * ss + 2.f * cc * bb;
                    p = ss * rr;
                    SSET(dreg, i + 1, gg + p);
                    gg = cc * rr - bb;
                    if (lane < 16) {
                        Z[lane][i + 1] = fmaf(cc, carry, ss * zlo);
                        carry = fmaf(cc, zlo, -ss * carry);
                    }
                    dI1 = dI; dI = dN; eI = eN; zlo = zN;
                }
                if (lane < 16) Z[lane][l] = carry;
                SSET(dreg, l, sget(dreg, l) - p);
                SSET(ereg, l, gg);
            }
        } else {
            // ---- QR sweeps ----
            for (;;) {
                int mq;
                {
                    float dnext = __shfl_down_sync(FULLMASK, dreg, 1);
                    bool stop = (lane >= lend && lane < l) &&
                        (ereg * ereg <= (EPS2 * fabsf(dnext)) * fabsf(dreg) + SAFMIN);
                    unsigned msk = __ballot_sync(FULLMASK, stop);
                    mq = msk ? (31 - __clz(msk)) + 1 : lend;
                }
                if (mq > lend) SSET(ereg, mq - 1, 0.f);
                float p = sget(dreg, l);
                if (mq == l) { l--; if (l >= lend) continue; break; }
                if (mq == l - 1) {
                    float rt1, rt2, cc, ss;
                    laev2(sget(dreg, l - 1), sget(ereg, l - 1), sget(dreg, l), rt1, rt2, cc, ss);
                    if (lane < 16) {
                        float t = Z[lane][l];
                        Z[lane][l]     = cc * t - ss * Z[lane][l - 1];
                        Z[lane][l - 1] = ss * t + cc * Z[lane][l - 1];
                    }
                    SSET(dreg, l - 1, rt1); SSET(dreg, l, rt2); SSET(ereg, l - 1, 0.f);
                    l -= 2; if (l >= lend) continue; break;
                }
                if (jtot >= nmaxit) break;
                jtot++;
                float el = sget(ereg, l - 1);
                float gg = __fdividef(sget(dreg, l - 1) - p, 2.f * el);
                float rr = sqrtf(fmaf(gg, gg, 1.f));
                gg = sget(dreg, mq) - p + __fdividef(el, gg + copysignf(rr, gg));
                float ss = 1.f, cc = 1.f; p = 0.f;
                float carry = (lane < 16) ? Z[lane][mq] : 0.f;
                float dI  = sget(dreg, mq);
                float eI  = sget(ereg, mq);
                float dI1 = sget(dreg, mq + 1);
                float zhi = (lane < 16) ? Z[lane][mq + 1] : 0.f;
                for (int i = mq; i < l; ++i) {
                    int i2 = (i + 2 <= l) ? i + 2 : l;
                    float eN  = sget(ereg, (i + 1 < l) ? i + 1 : l - 1);
                    float dN1 = sget(dreg, i2);
                    float zN  = (lane < 16 && i + 1 < l) ? Z[lane][i + 2] : 0.f;
                    float ff = ss * eI, bb = cc * eI;
                    lartg(gg, ff, cc, ss, rr);
                    if (i != mq) SSET(ereg, i - 1, rr);
                    gg = dI - p;
                    rr = (dI1 - gg) * ss + 2.f * cc * bb;
                    p = ss * rr;
                    SSET(dreg, i, gg + p);
                    gg = cc * rr - bb;
                    if (lane < 16) {
                        Z[lane][i] = fmaf(ss, zhi, cc * carry);
                        carry = fmaf(cc, zhi, -ss * carry);
                    }
                    dI = dI1; dI1 = dN1; eI = eN; zhi = zN;
                }
                if (lane < 16) Z[lane][l] = carry;
                SSET(dreg, l, sget(dreg, l) - p);
                SSET(ereg, l - 1, gg);
            }
        }
        if (iscale == 1) {
            float sc = anorm / SSFMAX;
            if (lane >= lsv && lane <= lendsv) dreg *= sc;
            if (lane >= lsv && lane < lendsv)  ereg *= sc;
        } else if (iscale == 2) {
            float sc = anorm / SSFMIN;
            if (lane >= lsv && lane <= lendsv) dreg *= sc;
            if (lane >= lsv && lane < lendsv)  ereg *= sc;
        }
    }

    // ---- argmax eigenvalue BEFORE back-transform ----
    float dv = (lane < 16) ? dreg : -3.4e38f;
    int idx = lane;
#pragma unroll
    for (int off = 16; off; off >>= 1) {
        float vo = __shfl_xor_sync(FULLMASK, dv, off);
        int io = __shfl_xor_sync(FULLMASK, idx, off);
        if (vo > dv || (vo == dv && io < idx)) { dv = vo; idx = io; }
    }
    int cmax = idx;
    float lam = sget(dreg, cmax);

    // ---- sormtr on the single needed column ----
    float v16 = (lane < 16) ? Z[lane][cmax] : 0.f;
    for (int i = 14; i >= 0; --i) {
        float ti = sget(taureg, i);
        if (ti != 0.f) {
            float vlane = (lane == i + 1) ? 1.f
                        : ((lane >= i + 2 && lane < 16) ? A[lane][i] : 0.f);
            float wj = wsum(vlane * v16) * ti;
            v16 = fmaf(-vlane, wj, v16);
        }
    }

    float tr = g_tr[slot];
    int o = slot & 31;
    if (lane == 0) out[slot] = 1.f / (1.f + expf(-(lam / tr - bias[o])));
    if (lane < 16) out[512 + slot * 16 + lane] = v16;
}

// ---------------------------------------------------------------------------
extern "C" void kernel_launch(void* const* d_in, const int* in_sizes, int n_in,
                              void* d_out, int out_size) {
    const float* in   = (const float*)d_in[0];
    const float* wts  = (const float*)d_in[1];
    const float* bias = (const float*)d_in[2];
    float* out = (float*)d_out;
    k1a<<<2048, 256>>>(in);
    k2_gram<<<512, 256>>>(wts);
    k3_eig<<<512, 32>>>(bias, out);
}

// round 9
// speedup vs baseline: 1.7373x; 1.0233x over previous
// SpectralCapsules R9: fuse k2 into k3 (gram phase + eig phase in one kernel;
// gram of block n overlaps eig of block m -> k2 hides in k3's stall shadow).
// k1a unchanged from R8.
#include <cuda_runtime.h>
#include <math.h>

#define FULLMASK 0xffffffffu

constexpr int Bb = 16;    // batch
constexpr int Mm = 256;   // H*W
constexpr int Cc = 544;   // channels = L*(P+1)

__device__ float g_Sp[Bb * 32 * 4 * 256]; // partial S per m-chunk

// ---------------------------------------------------------------------------
// K1a: partial S over 64 m per block (unchanged R8).
// ---------------------------------------------------------------------------
__global__ void __launch_bounds__(256) k1a(const float* __restrict__ in) {
    int blk = blockIdx.x;               // ((b*32+l)*4 + chunk)
    int chunk = blk & 3;
    int bl = blk >> 2;
    int b = bl >> 5, l = bl & 31;
    __shared__ float sp[64 * 16];
    __shared__ float sa2[64];
    __shared__ float red[4][16 * 17];
    int t = threadIdx.x;
    const float* base = in + (size_t)b * Mm * Cc + (size_t)chunk * 64 * Cc;
    {
        int mm = t >> 2, q = t & 3;
        const float4* src = (const float4*)(base + (size_t)mm * Cc + l * 16) + q;
        ((float4*)sp)[mm * 4 + q] = *src;
    }
    if (t < 64) {
        float a = base[(size_t)t * Cc + 512 + l];
        sa2[t] = a * a;
    }
    __syncthreads();
    int g = t >> 6, u = t & 63;
    int r0 = (u >> 3) * 2, c0 = (u & 7) * 2;
    float a00 = 0.f, a01 = 0.f, a10 = 0.f, a11 = 0.f;
#pragma unroll
    for (int mm = 0; mm < 16; ++mm) {
        int m = g * 16 + mm;
        float a2 = sa2[m];
        float2 vr = *(const float2*)&sp[m * 16 + r0];
        float2 vc = *(const float2*)&sp[m * 16 + c0];
        float t0 = a2 * vr.x, t1 = a2 * vr.y;
        a00 = fmaf(t0, vc.x, a00);
        a01 = fmaf(t0, vc.y, a01);
        a10 = fmaf(t1, vc.x, a10);
        a11 = fmaf(t1, vc.y, a11);
    }
    red[g][r0 * 17 + c0]           = a00;
    red[g][r0 * 17 + c0 + 1]       = a01;
    red[g][(r0 + 1) * 17 + c0]     = a10;
    red[g][(r0 + 1) * 17 + c0 + 1] = a11;
    __syncthreads();
    {
        int r = t >> 4, c = t & 15;
        int idx = r * 17 + c;
        g_Sp[blk * 256 + t] = ((red[0][idx] + red[1][idx]) + red[2][idx]) + red[3][idx];
    }
}

// ---------------------------------------------------------------------------
// helpers
// ---------------------------------------------------------------------------
__device__ __forceinline__ float wsum(float x) {
#pragma unroll
    for (int o = 16; o; o >>= 1) x += __shfl_xor_sync(FULLMASK, x, o);
    return x;
}
__device__ __forceinline__ float wmaxf(float x) {
#pragma unroll
    for (int o = 16; o; o >>= 1) x = fmaxf(x, __shfl_xor_sync(FULLMASK, x, o));
    return x;
}
__device__ __forceinline__ float sget(float v, int i) {
    return __shfl_sync(FULLMASK, v, i);
}
#define SSET(var, idx, val) do { float _v = (val); int _i = (idx); \
    if ((threadIdx.x & 31) == _i) var = _v; } while (0)

__device__ __forceinline__ void lartg(float f, float g, float& c, float& s, float& r) {
    if (g == 0.f)      { c = 1.f; s = 0.f; r = f; }
    else if (f == 0.f) { c = 0.f; s = copysignf(1.f, g); r = fabsf(g); }
    else {
        float t2 = fmaf(f, f, g * g);
        float rinv = rsqrtf(t2);
        float d = t2 * rinv;
        c = fabsf(f) * rinv;
        r = copysignf(d, f);
        s = g * rinv * copysignf(1.f, f);
    }
}

__device__ __forceinline__ void laev2(float a, float b, float c,
                                      float& rt1, float& rt2, float& cs1, float& sn1) {
    float sm = a + c, df = a - c;
    float adf = fabsf(df);
    float tb = b + b;
    float ab = fabsf(tb);
    float acmx, acmn;
    if (fabsf(a) > fabsf(c)) { acmx = a; acmn = c; } else { acmx = c; acmn = a; }
    float rt;
    if (adf > ab)      rt = adf * sqrtf(1.f + (ab / adf) * (ab / adf));
    else if (adf < ab) rt = ab * sqrtf(1.f + (adf / ab) * (adf / ab));
    else               rt = ab * sqrtf(2.f);
    int sgn1;
    if (sm < 0.f)      { rt1 = 0.5f * (sm - rt); sgn1 = -1; rt2 = (acmx / rt1) * acmn - (b / rt1) * b; }
    else if (sm > 0.f) { rt1 = 0.5f * (sm + rt); sgn1 = 1;  rt2 = (acmx / rt1) * acmn - (b / rt1) * b; }
    else               { rt1 = 0.5f * rt; rt2 = -0.5f * rt; sgn1 = 1; }
    float cs; int sgn2;
    if (df >= 0.f) { cs = df + rt; sgn2 = 1; } else { cs = df - rt; sgn2 = -1; }
    float acs = fabsf(cs);
    if (acs > ab) {
        float ct = -tb / cs;
        sn1 = 1.f / sqrtf(1.f + ct * ct);
        cs1 = ct * sn1;
    } else {
        if (ab == 0.f) { cs1 = 1.f; sn1 = 0.f; }
        else {
            float tn = -cs / tb;
            cs1 = 1.f / sqrtf(1.f + tn * tn);
            sn1 = tn * cs1;
        }
    }
    if (sgn1 == sgn2) { float tn = cs1; cs1 = -sn1; sn1 = tn; }
}

// ---------------------------------------------------------------------------
// K23: phase 1 = gram (256 threads), phase 2 = eig (warp 0 only).
// ---------------------------------------------------------------------------
__global__ void __launch_bounds__(256) k23(const float* __restrict__ wts,
                                           const float* __restrict__ bias,
                                           float* __restrict__ out) {
    __shared__ float sS[256];
    __shared__ float sH[256];
    __shared__ float sW[512];
    __shared__ float sG[256];
    __shared__ float A[16][17];
    __shared__ float Z[16][17];
    int t = threadIdx.x;
    int slot = blockIdx.x;              // b*32 + o
    int b = slot >> 5, o = slot & 31;

    // ---------------- phase 1: gram (== old k2, smem output) ----------------
    {
        int r = t >> 4, c = t & 15;
        int i = r >> 2, k = r & 3;
        int cb = c & ~3, km = c & 3;
        sW[t]       = wts[(((t >> 4)     ) * 32 + o) * 16 + (t & 15)];
        sW[t + 256] = wts[(((t >> 4) + 16) * 32 + o) * 16 + (t & 15)];
        const float* p0 = g_Sp + (size_t)(b * 32) * 1024 + t;
        float pre = ((p0[0] + p0[256]) + p0[512]) + p0[768];
        float g = 0.f;
        for (int l = 0; l < 32; ++l) {
            sS[t] = pre;
            __syncthreads();
            if (l < 31) {
                const float* pn = g_Sp + (size_t)(b * 32 + l + 1) * 1024 + t;
                pre = ((pn[0] + pn[256]) + pn[512]) + pn[768];
            }
            const float* wv = &sW[l * 16];
            float h = 0.f;
#pragma unroll
            for (int j = 0; j < 4; ++j) h = fmaf(sS[r * 16 + cb + j], wv[j * 4 + km], h);
            sH[t] = h;
            __syncthreads();
#pragma unroll
            for (int j = 0; j < 4; ++j) g = fmaf(wv[j * 4 + k], sH[(i * 4 + j) * 16 + c], g);
        }
        sG[t] = g;
        __syncthreads();
    }
    if (t >= 32) return;

    // ---------------- phase 2: eig on warp 0 (== old k3, G from smem) -------
    int lane = t;
    int lr = lane & 15;
    float tr;
    {
        float trp = 0.f;
        if (lane < 16) trp = sG[lane * 17];    // diagonal entries
        tr = wsum(trp);
    }
    if (lane < 16) {
#pragma unroll
        for (int j = 0; j < 16; ++j) A[lane][j] = 0.5f * (sG[lane * 16 + j] + sG[j * 16 + lane]);
#pragma unroll
        for (int j = 0; j < 16; ++j) Z[lane][j] = (lane == j) ? 1.f : 0.f;
    }
    __syncwarp();

    float dreg = 0.f, ereg = 0.f, taureg = 0.f;

    // ---- ssytrd (UPLO='L', unblocked) ----
    for (int i = 0; i < 15; ++i) {
        float alpha = A[i + 1][i];
        float colv = (lane >= i + 2 && lane < 16) ? A[lane][i] : 0.f;
        float xnorm = sqrtf(wsum(colv * colv));
        float taui = 0.f, ei = alpha;
        if (i < 14 && xnorm != 0.f) {
            float beta = -copysignf(sqrtf(fmaf(alpha, alpha, xnorm * xnorm)), alpha);
            taui = __fdividef(beta - alpha, beta);
            float sc = __fdividef(1.f, alpha - beta);
            float vlane = colv * sc;
            if (lane == i + 1) vlane = 1.f;
            ei = beta;
            float xr = 0.f;
#pragma unroll
            for (int j = 0; j < 16; ++j) {
                float vj = sget(vlane, j);
                xr = fmaf(A[lr][j], vj, xr);
            }
            xr = (lane >= i + 1 && lane < 16) ? xr * taui : 0.f;
            float dotxv = wsum(xr * vlane);
            float wr = fmaf(-0.5f * taui * dotxv, vlane, xr);
            __syncwarp();
#pragma unroll
            for (int j = 0; j < 16; ++j) {
                float vj = sget(vlane, j), wj = sget(wr, j);
                if (lane >= j && lane < 16) {
                    float val = fmaf(wr, -vj, fmaf(vlane, -wj, A[lane][j]));
                    A[lane][j] = val;
                    if (lane != j) A[j][lane] = val;
                }
            }
            __syncwarp();
            if (lane >= i + 2 && lane < 16) A[lane][i] = vlane;
            __syncwarp();
        }
        SSET(ereg, i, ei);
        SSET(taureg, i, taui);
    }
    if (lane < 16) dreg = A[lane][lane];

    // ---- ssteqr (COMPZ='I') ----
    const float EPS  = 5.9604645e-08f;
    const float EPS2 = 3.5527137e-15f;
    const float SAFMIN = 1.17549435e-38f;
    const float SSFMAX = 3.0744573e18f;
    const float SSFMIN = 3.0517578e-05f;
    int l1 = 0, jtot = 0;
    const int nmaxit = 480;

    while (l1 <= 15) {
        if (l1 > 0) SSET(ereg, l1 - 1, 0.f);
        int m;
        {
            float dnext = __shfl_down_sync(FULLMASK, dreg, 1);
            float tst = fabsf(ereg);
            bool stop = (lane >= l1 && lane < 15) &&
                (tst == 0.f || tst <= (sqrtf(fabsf(dreg)) * sqrtf(fabsf(dnext))) * EPS);
            unsigned msk = __ballot_sync(FULLMASK, stop);
            m = msk ? (__ffs(msk) - 1) : 15;
            if (m < 15) SSET(ereg, m, 0.f);
        }
        int l = l1, lsv = l1, lend = m, lendsv = m;
        l1 = m + 1;
        if (lend == l) continue;
        float av = (lane >= l && lane <= lend && lane < 16) ? fabsf(dreg) : 0.f;
        float ae = (lane >= l && lane < lend) ? fabsf(ereg) : 0.f;
        float anorm = wmaxf(fmaxf(av, ae));
        if (anorm == 0.f) continue;
        int iscale = 0;
        if (anorm > SSFMAX) {
            iscale = 1; float sc = SSFMAX / anorm;
            if (lane >= l && lane <= lend) dreg *= sc;
            if (lane >= l && lane < lend)  ereg *= sc;
        } else if (anorm < SSFMIN) {
            iscale = 2; float sc = SSFMIN / anorm;
            if (lane >= l && lane <= lend) dreg *= sc;
            if (lane >= l && lane < lend)  ereg *= sc;
        }
        if (fabsf(sget(dreg, lend)) < fabsf(sget(dreg, l))) { int tmp = l; l = lend; lend = tmp; }

        if (lend > l) {
            // ---- QL sweeps ----
            for (;;) {
                int mq;
                {
                    float dnext = __shfl_down_sync(FULLMASK, dreg, 1);
                    bool stop = (lane >= l && lane < lend) &&
                        (ereg * ereg <= (EPS2 * fabsf(dreg)) * fabsf(dnext) + SAFMIN);
                    unsigned msk = __ballot_sync(FULLMASK, stop);
                    mq = msk ? (__ffs(msk) - 1) : lend;
                }
                if (mq < lend) SSET(ereg, mq, 0.f);
                float p = sget(dreg, l);
                if (mq == l) { l++; if (l <= lend) continue; break; }
                if (mq == l + 1) {
                    float rt1, rt2, cc, ss;
                    laev2(sget(dreg, l), sget(ereg, l), sget(dreg, l + 1), rt1, rt2, cc, ss);
                    if (lane < 16) {
                        float tz = Z[lane][l + 1];
                        Z[lane][l + 1] = cc * tz - ss * Z[lane][l];
                        Z[lane][l]     = ss * tz + cc * Z[lane][l];
                    }
                    SSET(dreg, l, rt1); SSET(dreg, l + 1, rt2); SSET(ereg, l, 0.f);
                    l += 2; if (l <= lend) continue; break;
                }
                if (jtot >= nmaxit) break;
                jtot++;
                float el = sget(ereg, l);
                float gg = __fdividef(sget(dreg, l + 1) - p, 2.f * el);
                float rr = sqrtf(fmaf(gg, gg, 1.f));
                gg = sget(dreg, mq) - p + __fdividef(el, gg + copysignf(rr, gg));
                float ss = 1.f, cc = 1.f; p = 0.f;
                float carry = (lane < 16) ? Z[lane][mq] : 0.f;
                float dI1 = sget(dreg, mq);
                float eI  = sget(ereg, mq - 1);
                float dI  = sget(dreg, mq - 1);
                float zlo = (lane < 16) ? Z[lane][mq - 1] : 0.f;
                for (int i = mq - 1; i >= l; --i) {
                    int ip = (i - 1 >= l) ? i - 1 : l;
                    float eN = sget(ereg, ip);
                    float dN = sget(dreg, ip);
                    float zN = (lane < 16 && i - 1 >= l) ? Z[lane][i - 1] : 0.f;
                    float ff = ss * eI, bb = cc * eI;
                    lartg(gg, ff, cc, ss, rr);
                    if (i != mq - 1) SSET(ereg, i + 1, rr);
                    gg = dI1 - p;
                    rr = (dI - gg) * ss + 2.f * cc * bb;
                    p = ss * rr;
                    SSET(dreg, i + 1, gg + p);
                    gg = cc * rr - bb;
                    if (lane < 16) {
                        Z[lane][i + 1] = fmaf(cc, carry, ss * zlo);
                        carry = fmaf(cc, zlo, -ss * carry);
                    }
                    dI1 = dI; dI = dN; eI = eN; zlo = zN;
                }
                if (lane < 16) Z[lane][l] = carry;
                SSET(dreg, l, sget(dreg, l) - p);
                SSET(ereg, l, gg);
            }
        } else {
            // ---- QR sweeps ----
            for (;;) {
                int mq;
                {
                    float dnext = __shfl_down_sync(FULLMASK, dreg, 1);
                    bool stop = (lane >= lend && lane < l) &&
                        (ereg * ereg <= (EPS2 * fabsf(dnext)) * fabsf(dreg) + SAFMIN);
                    unsigned msk = __ballot_sync(FULLMASK, stop);
                    mq = msk ? (31 - __clz(msk)) + 1 : lend;
                }
                if (mq > lend) SSET(ereg, mq - 1, 0.f);
                float p = sget(dreg, l);
                if (mq == l) { l--; if (l >= lend) continue; break; }
                if (mq == l - 1) {
                    float rt1, rt2, cc, ss;
                    laev2(sget(dreg, l - 1), sget(ereg, l - 1), sget(dreg, l), rt1, rt2, cc, ss);
                    if (lane < 16) {
                        float tz = Z[lane][l];
                        Z[lane][l]     = cc * tz - ss * Z[lane][l - 1];
                        Z[lane][l - 1] = ss * tz + cc * Z[lane][l - 1];
                    }
                    SSET(dreg, l - 1, rt1); SSET(dreg, l, rt2); SSET(ereg, l - 1, 0.f);
                    l -= 2; if (l >= lend) continue; break;
                }
                if (jtot >= nmaxit) break;
                jtot++;
                float el = sget(ereg, l - 1);
                float gg = __fdividef(sget(dreg, l - 1) - p, 2.f * el);
                float rr = sqrtf(fmaf(gg, gg, 1.f));
                gg = sget(dreg, mq) - p + __fdividef(el, gg + copysignf(rr, gg));
                float ss = 1.f, cc = 1.f; p = 0.f;
                float carry = (lane < 16) ? Z[lane][mq] : 0.f;
                float dI  = sget(dreg, mq);
                float eI  = sget(ereg, mq);
                float dI1 = sget(dreg, mq + 1);
                float zhi = (lane < 16) ? Z[lane][mq + 1] : 0.f;
                for (int i = mq; i < l; ++i) {
                    int i2 = (i + 2 <= l) ? i + 2 : l;
                    float eN  = sget(ereg, (i + 1 < l) ? i + 1 : l - 1);
                    float dN1 = sget(dreg, i2);
                    float zN  = (lane < 16 && i + 1 < l) ? Z[lane][i + 2] : 0.f;
                    float ff = ss * eI, bb = cc * eI;
                    lartg(gg, ff, cc, ss, rr);
                    if (i != mq) SSET(ereg, i - 1, rr);
                    gg = dI - p;
                    rr = (dI1 - gg) * ss + 2.f * cc * bb;
                    p = ss * rr;
                    SSET(dreg, i, gg + p);
                    gg = cc * rr - bb;
                    if (lane < 16) {
                        Z[lane][i] = fmaf(ss, zhi, cc * carry);
                        carry = fmaf(cc, zhi, -ss * carry);
                    }
                    dI = dI1; dI1 = dN1; eI = eN; zhi = zN;
                }
                if (lane < 16) Z[lane][l] = carry;
                SSET(dreg, l, sget(dreg, l) - p);
                SSET(ereg, l - 1, gg);
            }
        }
        if (iscale == 1) {
            float sc = anorm / SSFMAX;
            if (lane >= lsv && lane <= lendsv) dreg *= sc;
            if (lane >= lsv && lane < lendsv)  ereg *= sc;
        } else if (iscale == 2) {
            float sc = anorm / SSFMIN;
            if (lane >= lsv && lane <= lendsv) dreg *= sc;
            if (lane >= lsv && lane < lendsv)  ereg *= sc;
        }
    }

    // ---- argmax eigenvalue BEFORE back-transform ----
    float dv = (lane < 16) ? dreg : -3.4e38f;
    int idx = lane;
#pragma unroll
    for (int off = 16; off; off >>= 1) {
        float vo = __shfl_xor_sync(FULLMASK, dv, off);
        int io = __shfl_xor_sync(FULLMASK, idx, off);
        if (vo > dv || (vo == dv && io < idx)) { dv = vo; idx = io; }
    }
    int cmax = idx;
    float lam = sget(dreg, cmax);

    // ---- sormtr on the single needed column ----
    float v16 = (lane < 16) ? Z[lane][cmax] : 0.f;
    for (int i = 14; i >= 0; --i) {
        float ti = sget(taureg, i);
        if (ti != 0.f) {
            float vlane = (lane == i + 1) ? 1.f
                        : ((lane >= i + 2 && lane < 16) ? A[lane][i] : 0.f);
            float wj = wsum(vlane * v16) * ti;
            v16 = fmaf(-vlane, wj, v16);
        }
    }

    if (lane == 0) out[slot] = 1.f / (1.f + expf(-(lam / tr - bias[o])));
    if (lane < 16) out[512 + slot * 16 + lane] = v16;
}

// ---------------------------------------------------------------------------
extern "C" void kernel_launch(void* const* d_in, const int* in_sizes, int n_in,
                              void* d_out, int out_size) {
    const float* in   = (const float*)d_in[0];
    const float* wts  = (const float*)d_in[1];
    const float* bias = (const float*)d_in[2];
    float* out = (float*)d_out;
    k1a<<<2048, 256>>>(in);
    k23<<<512, 256>>>(wts, bias, out);
}